// round 13
// baseline (speedup 1.0000x reference)
#include <cuda_runtime.h>
#include <cuda_bf16.h>
#include <cuda_fp16.h>
#include <cstdint>
#include <math.h>

#define BB 2
#define LL 2048
#define DD 1024
#define HH 16
#define DHH 64
#define MM (BB * LL)   // 4096
#define L2E 1.4426950408889634f

// ---------------------------------------------------------------------------
// Scratch (__device__ globals: allocation-free rule)
// ---------------------------------------------------------------------------
__device__ __half g_x16[MM * DD];        // x in fp16
__device__ __half g_ao16[MM * DD];       // attention output in fp16
__device__ __half g_wt16[4][DD * DD];    // transposed weights [which][n][k] fp16

__device__ __half g_q16[MM * DD];        // Q fp16, pre-scaled by 0.125
__device__ __half g_k16[MM * DD];        // K fp16
__device__ __half g_v16[MM * DD];        // V fp16

// ---------------------------------------------------------------------------
// PTX helpers (portable sm_80+ subset; plain sm_103 target — no tcgen05)
// ---------------------------------------------------------------------------
__device__ __forceinline__ uint32_t smem_to_u32(const void* p) {
    uint32_t a;
    asm("{ .reg .u64 t; cvta.to.shared.u64 t, %1; cvt.u32.u64 %0, t; }"
        : "=r"(a) : "l"(p));
    return a;
}
__device__ __forceinline__ void cpasync16(uint32_t s, const void* g) {
    asm volatile("cp.async.cg.shared.global [%0], [%1], 16;" :: "r"(s), "l"(g));
}
__device__ __forceinline__ void cpcommit() {
    asm volatile("cp.async.commit_group;" ::: "memory");
}
template <int N>
__device__ __forceinline__ void cpwait() {
    asm volatile("cp.async.wait_group %0;" :: "n"(N) : "memory");
}
__device__ __forceinline__ void ldsm4(uint32_t* r, uint32_t addr) {
    asm volatile("ldmatrix.sync.aligned.m8n8.x4.shared.b16 {%0,%1,%2,%3}, [%4];"
                 : "=r"(r[0]), "=r"(r[1]), "=r"(r[2]), "=r"(r[3]) : "r"(addr));
}
__device__ __forceinline__ void ldsm4t(uint32_t* r, uint32_t addr) {
    asm volatile("ldmatrix.sync.aligned.m8n8.x4.trans.shared.b16 {%0,%1,%2,%3}, [%4];"
                 : "=r"(r[0]), "=r"(r[1]), "=r"(r[2]), "=r"(r[3]) : "r"(addr));
}
__device__ __forceinline__ void mma_f16(float* d, const uint32_t* a, const uint32_t* b) {
    asm volatile(
        "mma.sync.aligned.m16n8k16.row.col.f32.f16.f16.f32 "
        "{%0,%1,%2,%3}, {%4,%5,%6,%7}, {%8,%9}, {%0,%1,%2,%3};"
        : "+f"(d[0]), "+f"(d[1]), "+f"(d[2]), "+f"(d[3])
        : "r"(a[0]), "r"(a[1]), "r"(a[2]), "r"(a[3]), "r"(b[0]), "r"(b[1]));
}
__device__ __forceinline__ uint32_t cvt_f16x2(float hi, float lo) {
    uint32_t r;
    asm volatile("cvt.rn.f16x2.f32 %0, %1, %2;" : "=r"(r) : "f"(hi), "f"(lo));
    return r;
}
__device__ __forceinline__ uint32_t ex2_f16x2(uint32_t x) {
    uint32_t r;
    asm volatile("ex2.approx.f16x2 %0, %1;" : "=r"(r) : "r"(x));
    return r;
}

// ---------------------------------------------------------------------------
// Prep kernels
// ---------------------------------------------------------------------------
__global__ __launch_bounds__(256) void xconv_kernel(const float* __restrict__ in)
{
    int i = blockIdx.x * blockDim.x + threadIdx.x;
    float4 v = ((const float4*)in)[i];
    __half2* hp = (__half2*)g_x16;
    hp[2 * i]     = __floats2half2_rn(v.x, v.y);
    hp[2 * i + 1] = __floats2half2_rn(v.z, v.w);
}

// Transpose weights: W[K][N] -> Wt[n][k] fp16
__global__ __launch_bounds__(1024) void wconv_kernel(const float* __restrict__ wq,
                                                     const float* __restrict__ wk,
                                                     const float* __restrict__ wv,
                                                     const float* __restrict__ wo)
{
    __shared__ float t[32][33];
    int which = blockIdx.z;
    const float* w = (which == 0) ? wq : (which == 1) ? wk : (which == 2) ? wv : wo;
    int kk = blockIdx.y * 32 + threadIdx.y;
    int nn = blockIdx.x * 32 + threadIdx.x;
    t[threadIdx.y][threadIdx.x] = w[kk * DD + nn];
    __syncthreads();
    int on = blockIdx.x * 32 + threadIdx.y;
    int ok = blockIdx.y * 32 + threadIdx.x;
    g_wt16[which][on * DD + ok] = __float2half_rn(t[threadIdx.x][threadIdx.y]);
}

// ---------------------------------------------------------------------------
// Single-pass fp16 HMMA GEMM: C[128,128 tile] = A @ Wt^T + bias
// 128 threads, warp grid 2(m)x2(n), warp tile 64x64, BK=64, 3-stage cp.async,
// fragment double-buffering (ldsm for ks+1 issued before HMMAs of ks).
// mode 0: fp32 out; mode 1: fp16 out *0.125 (Q); mode 2: fp16 out (K/V)
// ---------------------------------------------------------------------------
#define BK 64
#define APITCH 72
#define BUF_BYTES (128 * APITCH * 2)        // 18432 per operand buffer
#define GEMM_STAGE (2 * BUF_BYTES)          // 36864 (A + B)
#define GEMM_SMEM_BYTES (3 * GEMM_STAGE)    // 110592 -> 2 CTAs/SM

__device__ __forceinline__ void load_stage(uint32_t sbase, int stage,
                                           const __half* __restrict__ A,
                                           const __half* __restrict__ B,
                                           int m0, int n0, int k0, int tid)
{
    uint32_t so = sbase + stage * GEMM_STAGE;
#pragma unroll
    for (int j = 0; j < 8; j++) {
        int c = tid + (j << 7);                 // 0..1023
        int row = c >> 3;                       // 0..127
        int col = (c & 7) << 3;                 // 0..56
        uint32_t soff = (uint32_t)(row * APITCH + col) * 2;
        cpasync16(so + 0 * BUF_BYTES + soff, A + (size_t)(m0 + row) * DD + k0 + col);
        cpasync16(so + 1 * BUF_BYTES + soff, B + (size_t)(n0 + row) * DD + k0 + col);
    }
}

__device__ __forceinline__ void gemm_tc_body(const __half* __restrict__ A,
                                             const __half* __restrict__ B,
                                             const float* __restrict__ bias,
                                             float* __restrict__ C,
                                             int mode, __half* o16)
{
    extern __shared__ char smem[];
    const uint32_t sbase = smem_to_u32(smem);

    const int tid = threadIdx.x;
    const int lane = tid & 31;
    const int wid = tid >> 5;           // 0..3
    const int wm = (wid >> 1) * 64;     // 0 or 64
    const int wn = (wid & 1) * 64;      // 0 or 64
    const int m0 = blockIdx.y * 128;
    const int n0 = blockIdx.x * 128;

    const int a_row = wm + (lane & 15);
    const int a_col = (lane >> 4) << 3;
    const int b_row = wn + ((lane >> 4) << 3) + (lane & 7);
    const int b_col = ((lane >> 3) & 1) << 3;

    float acc[4][8][4];
#pragma unroll
    for (int i = 0; i < 4; i++)
#pragma unroll
        for (int j = 0; j < 8; j++)
#pragma unroll
            for (int r = 0; r < 4; r++) acc[i][j][r] = 0.f;

    load_stage(sbase, 0, A, B, m0, n0, 0, tid);
    cpcommit();
    load_stage(sbase, 1, A, B, m0, n0, BK, tid);
    cpcommit();

    // fragment double buffers
    uint32_t ah[2][4][4], bh[2][4][4];

    const int NT = DD / BK;             // 16
    int st_idx = 0;
    for (int kt = 0; kt < NT; kt++) {
        if (kt + 2 < NT) {
            int ps = st_idx + 2; if (ps >= 3) ps -= 3;
            load_stage(sbase, ps, A, B, m0, n0, (kt + 2) * BK, tid);
            cpcommit();
            cpwait<2>();
        } else if (kt + 1 < NT) {
            cpwait<1>();
        } else {
            cpwait<0>();
        }
        __syncthreads();

        const uint32_t st = sbase + st_idx * GEMM_STAGE;

        // prime fragments for ks=0
#pragma unroll
        for (int mt = 0; mt < 4; mt++) {
            uint32_t off = (uint32_t)((a_row + mt * 16) * APITCH + a_col) * 2;
            ldsm4(ah[0][mt], st + 0 * BUF_BYTES + off);
        }
#pragma unroll
        for (int nt2 = 0; nt2 < 4; nt2++) {
            uint32_t off = (uint32_t)((b_row + nt2 * 16) * APITCH + b_col) * 2;
            ldsm4(bh[0][nt2], st + 1 * BUF_BYTES + off);
        }

#pragma unroll
        for (int ks = 0; ks < 4; ks++) {
            const int cur = ks & 1;
            const int nxt = cur ^ 1;
            if (ks < 3) {
                const int kofs = (ks + 1) * 16;
#pragma unroll
                for (int mt = 0; mt < 4; mt++) {
                    uint32_t off = (uint32_t)((a_row + mt * 16) * APITCH + kofs + a_col) * 2;
                    ldsm4(ah[nxt][mt], st + 0 * BUF_BYTES + off);
                }
#pragma unroll
                for (int nt2 = 0; nt2 < 4; nt2++) {
                    uint32_t off = (uint32_t)((b_row + nt2 * 16) * APITCH + kofs + b_col) * 2;
                    ldsm4(bh[nxt][nt2], st + 1 * BUF_BYTES + off);
                }
            }
#pragma unroll
            for (int mt = 0; mt < 4; mt++)
#pragma unroll
                for (int nt = 0; nt < 8; nt++)
                    mma_f16(acc[mt][nt], ah[cur][mt], &bh[cur][nt >> 1][(nt & 1) * 2]);
        }
        __syncthreads();
        if (++st_idx == 3) st_idx = 0;
    }

    const float sc = (mode == 1) ? 0.125f : 1.0f;
#pragma unroll
    for (int mt = 0; mt < 4; mt++) {
        int row = m0 + wm + mt * 16 + (lane >> 2);
#pragma unroll
        for (int nt = 0; nt < 8; nt++) {
            int col = n0 + wn + nt * 8 + 2 * (lane & 3);
            float b0 = bias[col], b1 = bias[col + 1];
            float v0 = acc[mt][nt][0] + b0, v1 = acc[mt][nt][1] + b1;
            float v2 = acc[mt][nt][2] + b0, v3 = acc[mt][nt][3] + b1;
            size_t off0 = (size_t)row * DD + col;
            size_t off1 = (size_t)(row + 8) * DD + col;
            if (mode == 0) {
                *(float2*)(C + off0) = make_float2(v0, v1);
                *(float2*)(C + off1) = make_float2(v2, v3);
            } else {
                v0 *= sc; v1 *= sc; v2 *= sc; v3 *= sc;
                *(__half2*)(o16 + off0) = __floats2half2_rn(v0, v1);
                *(__half2*)(o16 + off1) = __floats2half2_rn(v2, v3);
            }
        }
    }
}

__global__ __launch_bounds__(128, 2)
void gemm_qkv_tc(const float* __restrict__ bq, const float* __restrict__ bk,
                 const float* __restrict__ bv)
{
    const int z = blockIdx.z;
    if (z == 0)
        gemm_tc_body(g_x16, g_wt16[0], bq, nullptr, 1, g_q16);
    else if (z == 1)
        gemm_tc_body(g_x16, g_wt16[1], bk, nullptr, 2, g_k16);
    else
        gemm_tc_body(g_x16, g_wt16[2], bv, nullptr, 2, g_v16);
}

__global__ __launch_bounds__(128, 2)
void gemm_out_tc(const float* __restrict__ bo, float* __restrict__ out)
{
    gemm_tc_body(g_ao16, g_wt16[3], bo, out, 0, nullptr);
}

// ---------------------------------------------------------------------------
// Tensor-core flash attention, causal, single-pass fp16.  (R8/R10-12 version)
// CTA: 64 q rows, 128 threads, 2-stage cp.async K/V pipeline, 4 CTAs/SM.
// Ones-column in V col 64 carries the row-sum l through the PV MMA.
// ---------------------------------------------------------------------------
#define VPITCH 88
#define AQ 0
#define AST 8192
#define SK 0
#define SV 8192
#define ASTAGE (8192 + 64 * VPITCH * 2)     // 19456
#define ATT_SMEM (AST + 2 * ASTAGE)         // 47104

__device__ __forceinline__ void attn_load_stage(uint32_t sb, int stage,
                                                const __half* gk,
                                                const __half* gv,
                                                int k0, int tid)
{
    uint32_t so = sb + AST + stage * ASTAGE;
#pragma unroll
    for (int i = 0; i < 4; i++) {
        int idx = tid + (i << 7);
        int r = idx >> 3, c = idx & 7;
        uint32_t offk = 128u * r + 16u * (c ^ (r & 7));
        size_t g = (size_t)(k0 + r) * DD + c * 8;
        cpasync16(so + SK + offk, gk + g);
        uint32_t offv = (uint32_t)(r * VPITCH + c * 8) * 2;
        cpasync16(so + SV + offv, gv + g);
    }
}

__global__ __launch_bounds__(128, 4) void attn_tc_kernel()
{
    extern __shared__ char sm[];
    const uint32_t sb = smem_to_u32(sm);
    const int tid = threadIdx.x;
    const int lane = tid & 31;
    const int wid = tid >> 5;
    const int bh = blockIdx.y;
    const int b = bh >> 4;
    const int h = bh & 15;
    const int q0 = (int)(gridDim.x - 1 - blockIdx.x) * 64;   // big tiles first

    const size_t tok0 = (size_t)(b * LL);
    const __half* gq = g_q16 + (tok0 + q0) * DD + h * 64;
    const __half* gk = g_k16 + tok0 * DD + h * 64;
    const __half* gv = g_v16 + tok0 * DD + h * 64;

    // kick off stage 0 loads immediately
    attn_load_stage(sb, 0, gk, gv, 0, tid);
    cpcommit();

    // V pad cols 64..87 in BOTH stages: zeros
#pragma unroll
    for (int s = 0; s < 2; s++) {
        char* vb = sm + AST + s * ASTAGE;
        for (int i = tid; i < 64 * 3; i += 128) {
            int r = i / 3, c = i % 3;
            uint32_t off = (uint32_t)(r * VPITCH + 64 + 8 * c) * 2;
            *(uint4*)(vb + SV + off) = make_uint4(0, 0, 0, 0);
        }
    }
    __syncthreads();   // zero-fill visible before ones-column write
#pragma unroll
    for (int s = 0; s < 2; s++) {
        char* vb = sm + AST + s * ASTAGE;
        if (tid < 64) ((__half*)(vb + SV))[tid * VPITCH + 64] = __float2half(1.0f);
    }

    // Load Q tile (swizzled, regular loads)
#pragma unroll
    for (int i = 0; i < 4; i++) {
        int idx = tid + (i << 7);
        int r = idx >> 3, c = idx & 7;
        uint32_t off = 128u * r + 16u * (c ^ (r & 7));
        *(uint4*)(sm + AQ + off) = *(const uint4*)(gq + (size_t)r * DD + c * 8);
    }

    const int arow = 16 * wid + (lane & 15);
    const int ac = lane >> 4;
    const int asw = arow & 7;
    const int brow_in = ((lane >> 4) << 3) + (lane & 7);
    const int bc = (lane >> 3) & 1;
    const int bsw = brow_in & 7;
    const int vrow_in = (lane & 7) + ((lane >> 3) & 1) * 8;
    const int vnc = (lane >> 4);

    float oacc[9][4];
#pragma unroll
    for (int i = 0; i < 9; i++)
#pragma unroll
        for (int j = 0; j < 4; j++) oacc[i][j] = 0.f;
    float m2[2] = {-1e30f, -1e30f};

    const int nk = (q0 >> 6) + 1;
    for (int kt = 0; kt < nk; kt++) {
        if (kt + 1 < nk) {
            attn_load_stage(sb, (kt + 1) & 1, gk, gv, (kt + 1) * 64, tid);
            cpcommit();
            cpwait<1>();
        } else {
            cpwait<0>();
        }
        __syncthreads();
        const uint32_t st = sb + AST + (kt & 1) * ASTAGE;

        // ---- S = Q K^T (single-pass fp16), 16x64 per warp ----
        float sacc[8][4];
#pragma unroll
        for (int i = 0; i < 8; i++)
#pragma unroll
            for (int j = 0; j < 4; j++) sacc[i][j] = 0.f;

#pragma unroll
        for (int ks = 0; ks < 4; ks++) {
            uint32_t qf[4], kf[4][4];
            uint32_t ca = 16u * (uint32_t)((2 * ks + ac) ^ asw);
            ldsm4(qf, sb + AQ + 128u * arow + ca);
            uint32_t cb = 16u * (uint32_t)((2 * ks + bc) ^ bsw);
#pragma unroll
            for (int np = 0; np < 4; np++)
                ldsm4(kf[np], st + SK + 128u * (16 * np + brow_in) + cb);
#pragma unroll
            for (int nt = 0; nt < 8; nt++)
                mma_f16(sacc[nt], qf, &kf[nt >> 1][(nt & 1) * 2]);
        }

        // ---- causal mask (diagonal tile only) ----
        if (kt == nk - 1) {
            const int r0g = 16 * wid + (lane >> 2);
#pragma unroll
            for (int nt = 0; nt < 8; nt++) {
                int kc = 8 * nt + 2 * (lane & 3);
                if (kc > r0g)     sacc[nt][0] = -1e30f;
                if (kc + 1 > r0g) sacc[nt][1] = -1e30f;
                if (kc > r0g + 8)     sacc[nt][2] = -1e30f;
                if (kc + 1 > r0g + 8) sacc[nt][3] = -1e30f;
            }
        }

        // ---- online softmax (log2 domain), P in f16x2 ----
        float mx0 = -1e30f, mx1 = -1e30f;
#pragma unroll
        for (int nt = 0; nt < 8; nt++) {
            mx0 = fmaxf(mx0, fmaxf(sacc[nt][0], sacc[nt][1]));
            mx1 = fmaxf(mx1, fmaxf(sacc[nt][2], sacc[nt][3]));
        }
        mx0 = fmaxf(mx0, __shfl_xor_sync(0xffffffffu, mx0, 1));
        mx0 = fmaxf(mx0, __shfl_xor_sync(0xffffffffu, mx0, 2));
        mx1 = fmaxf(mx1, __shfl_xor_sync(0xffffffffu, mx1, 1));
        mx1 = fmaxf(mx1, __shfl_xor_sync(0xffffffffu, mx1, 2));
        float m2n0 = fmaxf(m2[0], mx0 * L2E);
        float m2n1 = fmaxf(m2[1], mx1 * L2E);
        float al0 = exp2f(m2[0] - m2n0);
        float al1 = exp2f(m2[1] - m2n1);
        m2[0] = m2n0; m2[1] = m2n1;

        uint32_t pf[4][4];
#pragma unroll
        for (int ks = 0; ks < 4; ks++) {
            pf[ks][0] = ex2_f16x2(cvt_f16x2(fmaf(sacc[2*ks][1],   L2E, -m2n0),
                                            fmaf(sacc[2*ks][0],   L2E, -m2n0)));
            pf[ks][1] = ex2_f16x2(cvt_f16x2(fmaf(sacc[2*ks][3],   L2E, -m2n1),
                                            fmaf(sacc[2*ks][2],   L2E, -m2n1)));
            pf[ks][2] = ex2_f16x2(cvt_f16x2(fmaf(sacc[2*ks+1][1], L2E, -m2n0),
                                            fmaf(sacc[2*ks+1][0], L2E, -m2n0)));
            pf[ks][3] = ex2_f16x2(cvt_f16x2(fmaf(sacc[2*ks+1][3], L2E, -m2n1),
                                            fmaf(sacc[2*ks+1][2], L2E, -m2n1)));
        }
#pragma unroll
        for (int nt = 0; nt < 9; nt++) {
            oacc[nt][0] *= al0; oacc[nt][1] *= al0;
            oacc[nt][2] *= al1; oacc[nt][3] *= al1;
        }

        // ---- O += P @ V (single-pass fp16; n=72 incl. ones column) ----
#pragma unroll
        for (int ks = 0; ks < 4; ks++) {
            const uint32_t vrow = (uint32_t)(16 * ks + vrow_in) * (VPITCH * 2);
#pragma unroll
            for (int np = 0; np < 5; np++) {
                uint32_t vf[4];
                uint32_t voff = vrow + 16u * (uint32_t)(2 * np + vnc);
                ldsm4t(vf, st + SV + voff);
                mma_f16(oacc[2 * np], pf[ks], &vf[0]);
                if (np < 4) mma_f16(oacc[2 * np + 1], pf[ks], &vf[2]);
            }
        }
        __syncthreads();
    }

    // ---- normalize and store fp16 (out-proj operand) ----
    const int src = lane & ~3;
    float l0 = __shfl_sync(0xffffffffu, oacc[8][0], src);
    float l1 = __shfl_sync(0xffffffffu, oacc[8][2], src);
    float i0 = 1.0f / l0;
    float i1 = 1.0f / l1;
    const int row0 = q0 + 16 * wid + (lane >> 2);
    __half* base16 = g_ao16 + tok0 * DD + h * 64;
#pragma unroll
    for (int nt = 0; nt < 8; nt++) {
        int col = 8 * nt + 2 * (lane & 3);
        size_t off0 = (size_t)row0 * DD + col;
        size_t off1 = (size_t)(row0 + 8) * DD + col;
        *(__half2*)(base16 + off0) = __floats2half2_rn(oacc[nt][0] * i0, oacc[nt][1] * i0);
        *(__half2*)(base16 + off1) = __floats2half2_rn(oacc[nt][2] * i1, oacc[nt][3] * i1);
    }
}

// ---------------------------------------------------------------------------
extern "C" void kernel_launch(void* const* d_in, const int* in_sizes, int n_in,
                              void* d_out, int out_size)
{
    (void)in_sizes; (void)n_in; (void)out_size;
    const float* x  = (const float*)d_in[0];
    const float* wq = (const float*)d_in[2];
    const float* bq = (const float*)d_in[3];
    const float* wk = (const float*)d_in[4];
    const float* bk = (const float*)d_in[5];
    const float* wv = (const float*)d_in[6];
    const float* bv = (const float*)d_in[7];
    const float* wo = (const float*)d_in[8];
    const float* bo = (const float*)d_in[9];
    float* out = (float*)d_out;

    cudaFuncSetAttribute(gemm_qkv_tc, cudaFuncAttributeMaxDynamicSharedMemorySize,
                         GEMM_SMEM_BYTES);
    cudaFuncSetAttribute(gemm_out_tc, cudaFuncAttributeMaxDynamicSharedMemorySize,
                         GEMM_SMEM_BYTES);
    cudaFuncSetAttribute(attn_tc_kernel, cudaFuncAttributeMaxDynamicSharedMemorySize,
                         ATT_SMEM);

    xconv_kernel<<<(MM * DD / 4) / 256, 256>>>(x);
    wconv_kernel<<<dim3(32, 32, 4), dim3(32, 32)>>>(wq, wk, wv, wo);
    gemm_qkv_tc<<<dim3(DD / 128, MM / 128, 3), 128, GEMM_SMEM_BYTES>>>(bq, bk, bv);
    attn_tc_kernel<<<dim3(LL / 64, BB * HH), 128, ATT_SMEM>>>();
    gemm_out_tc<<<dim3(DD / 128, MM / 128), 128, GEMM_SMEM_BYTES>>>(bo, out);
}

// round 14
// speedup vs baseline: 1.0112x; 1.0112x over previous
#include <cuda_runtime.h>
#include <cuda_bf16.h>
#include <cuda_fp16.h>
#include <cstdint>
#include <math.h>

#define BB 2
#define LL 2048
#define DD 1024
#define HH 16
#define DHH 64
#define MM (BB * LL)   // 4096
#define L2E 1.4426950408889634f

// ---------------------------------------------------------------------------
// Scratch (__device__ globals: allocation-free rule)
// ---------------------------------------------------------------------------
__device__ __half g_x16[MM * DD];        // x in fp16
__device__ __half g_ao16[MM * DD];       // attention output in fp16
__device__ __half g_wt16[4][DD * DD];    // transposed weights [which][n][k] fp16

__device__ __half g_q16[MM * DD];        // Q fp16, pre-scaled by 0.125
__device__ __half g_k16[MM * DD];        // K fp16
__device__ __half g_v16[MM * DD];        // V fp16

// ---------------------------------------------------------------------------
// PTX helpers (portable sm_80+ subset; plain sm_103 target — no tcgen05)
// ---------------------------------------------------------------------------
__device__ __forceinline__ uint32_t smem_to_u32(const void* p) {
    uint32_t a;
    asm("{ .reg .u64 t; cvta.to.shared.u64 t, %1; cvt.u32.u64 %0, t; }"
        : "=r"(a) : "l"(p));
    return a;
}
__device__ __forceinline__ void cpasync16(uint32_t s, const void* g) {
    asm volatile("cp.async.cg.shared.global [%0], [%1], 16;" :: "r"(s), "l"(g));
}
__device__ __forceinline__ void cpcommit() {
    asm volatile("cp.async.commit_group;" ::: "memory");
}
template <int N>
__device__ __forceinline__ void cpwait() {
    asm volatile("cp.async.wait_group %0;" :: "n"(N) : "memory");
}
__device__ __forceinline__ void ldsm4(uint32_t* r, uint32_t addr) {
    asm volatile("ldmatrix.sync.aligned.m8n8.x4.shared.b16 {%0,%1,%2,%3}, [%4];"
                 : "=r"(r[0]), "=r"(r[1]), "=r"(r[2]), "=r"(r[3]) : "r"(addr));
}
__device__ __forceinline__ void ldsm4t(uint32_t* r, uint32_t addr) {
    asm volatile("ldmatrix.sync.aligned.m8n8.x4.trans.shared.b16 {%0,%1,%2,%3}, [%4];"
                 : "=r"(r[0]), "=r"(r[1]), "=r"(r[2]), "=r"(r[3]) : "r"(addr));
}
__device__ __forceinline__ void mma_f16(float* d, const uint32_t* a, const uint32_t* b) {
    asm volatile(
        "mma.sync.aligned.m16n8k16.row.col.f32.f16.f16.f32 "
        "{%0,%1,%2,%3}, {%4,%5,%6,%7}, {%8,%9}, {%0,%1,%2,%3};"
        : "+f"(d[0]), "+f"(d[1]), "+f"(d[2]), "+f"(d[3])
        : "r"(a[0]), "r"(a[1]), "r"(a[2]), "r"(a[3]), "r"(b[0]), "r"(b[1]));
}
__device__ __forceinline__ uint32_t cvt_f16x2(float hi, float lo) {
    uint32_t r;
    asm volatile("cvt.rn.f16x2.f32 %0, %1, %2;" : "=r"(r) : "f"(hi), "f"(lo));
    return r;
}
__device__ __forceinline__ uint32_t ex2_f16x2(uint32_t x) {
    uint32_t r;
    asm volatile("ex2.approx.f16x2 %0, %1;" : "=r"(r) : "r"(x));
    return r;
}

// ---------------------------------------------------------------------------
// Prep kernels
// ---------------------------------------------------------------------------
__global__ __launch_bounds__(256) void xconv_kernel(const float* __restrict__ in)
{
    int i = blockIdx.x * blockDim.x + threadIdx.x;
    float4 v = ((const float4*)in)[i];
    __half2* hp = (__half2*)g_x16;
    hp[2 * i]     = __floats2half2_rn(v.x, v.y);
    hp[2 * i + 1] = __floats2half2_rn(v.z, v.w);
}

// Transpose weights: W[K][N] -> Wt[n][k] fp16
__global__ __launch_bounds__(1024) void wconv_kernel(const float* __restrict__ wq,
                                                     const float* __restrict__ wk,
                                                     const float* __restrict__ wv,
                                                     const float* __restrict__ wo)
{
    __shared__ float t[32][33];
    int which = blockIdx.z;
    const float* w = (which == 0) ? wq : (which == 1) ? wk : (which == 2) ? wv : wo;
    int kk = blockIdx.y * 32 + threadIdx.y;
    int nn = blockIdx.x * 32 + threadIdx.x;
    t[threadIdx.y][threadIdx.x] = w[kk * DD + nn];
    __syncthreads();
    int on = blockIdx.x * 32 + threadIdx.y;
    int ok = blockIdx.y * 32 + threadIdx.x;
    g_wt16[which][on * DD + ok] = __float2half_rn(t[threadIdx.x][threadIdx.y]);
}

// ---------------------------------------------------------------------------
// Single-pass fp16 HMMA GEMM (R12 config): C[128,128 tile] = A @ Wt^T + bias
// 128 threads, warp grid 2(m)x2(n), warp tile 64x64, BK=64, 2-stage cp.async,
// 3 CTAs/SM.
// mode 0: fp32 out; mode 1: fp16 out *0.125 (Q); mode 2: fp16 out (K/V)
// ---------------------------------------------------------------------------
#define BK 64
#define APITCH 72
#define BUF_BYTES (128 * APITCH * 2)        // 18432 per operand buffer
#define GEMM_STAGE (2 * BUF_BYTES)          // 36864 (A + B)
#define GEMM_SMEM_BYTES (2 * GEMM_STAGE)    // 73728 -> 3 CTAs/SM

__device__ __forceinline__ void load_stage(uint32_t sbase, int stage,
                                           const __half* __restrict__ A,
                                           const __half* __restrict__ B,
                                           int m0, int n0, int k0, int tid)
{
    uint32_t so = sbase + stage * GEMM_STAGE;
#pragma unroll
    for (int j = 0; j < 8; j++) {
        int c = tid + (j << 7);                 // 0..1023
        int row = c >> 3;                       // 0..127
        int col = (c & 7) << 3;                 // 0..56
        uint32_t soff = (uint32_t)(row * APITCH + col) * 2;
        cpasync16(so + 0 * BUF_BYTES + soff, A + (size_t)(m0 + row) * DD + k0 + col);
        cpasync16(so + 1 * BUF_BYTES + soff, B + (size_t)(n0 + row) * DD + k0 + col);
    }
}

__device__ __forceinline__ void gemm_tc_body(const __half* __restrict__ A,
                                             const __half* __restrict__ B,
                                             const float* __restrict__ bias,
                                             float* __restrict__ C,
                                             int mode, __half* o16)
{
    extern __shared__ char smem[];
    const uint32_t sbase = smem_to_u32(smem);

    const int tid = threadIdx.x;
    const int lane = tid & 31;
    const int wid = tid >> 5;           // 0..3
    const int wm = (wid >> 1) * 64;     // 0 or 64
    const int wn = (wid & 1) * 64;      // 0 or 64
    const int m0 = blockIdx.y * 128;
    const int n0 = blockIdx.x * 128;

    const int a_row = wm + (lane & 15);
    const int a_col = (lane >> 4) << 3;
    const int b_row = wn + ((lane >> 4) << 3) + (lane & 7);
    const int b_col = ((lane >> 3) & 1) << 3;

    float acc[4][8][4];
#pragma unroll
    for (int i = 0; i < 4; i++)
#pragma unroll
        for (int j = 0; j < 8; j++)
#pragma unroll
            for (int r = 0; r < 4; r++) acc[i][j][r] = 0.f;

    load_stage(sbase, 0, A, B, m0, n0, 0, tid);
    cpcommit();
    load_stage(sbase, 1, A, B, m0, n0, BK, tid);
    cpcommit();

    const int NT = DD / BK;             // 16
    for (int kt = 0; kt < NT; kt++) {
        if (kt + 2 < NT) {
            cpwait<1>();
        } else {
            cpwait<0>();
        }
        __syncthreads();

        const uint32_t st = sbase + (kt & 1) * GEMM_STAGE;
#pragma unroll
        for (int ks = 0; ks < 4; ks++) {
            const int kofs = ks * 16;
            uint32_t ah[4][4], bh[4][4];
#pragma unroll
            for (int mt = 0; mt < 4; mt++) {
                uint32_t off = (uint32_t)((a_row + mt * 16) * APITCH + kofs + a_col) * 2;
                ldsm4(ah[mt], st + 0 * BUF_BYTES + off);
            }
#pragma unroll
            for (int nt2 = 0; nt2 < 4; nt2++) {
                uint32_t off = (uint32_t)((b_row + nt2 * 16) * APITCH + kofs + b_col) * 2;
                ldsm4(bh[nt2], st + 1 * BUF_BYTES + off);
            }
#pragma unroll
            for (int mt = 0; mt < 4; mt++)
#pragma unroll
                for (int nt = 0; nt < 8; nt++)
                    mma_f16(acc[mt][nt], ah[mt], &bh[nt >> 1][(nt & 1) * 2]);
        }
        __syncthreads();
        if (kt + 2 < NT) {
            load_stage(sbase, kt & 1, A, B, m0, n0, (kt + 2) * BK, tid);
            cpcommit();
        }
    }

    const float sc = (mode == 1) ? 0.125f : 1.0f;
#pragma unroll
    for (int mt = 0; mt < 4; mt++) {
        int row = m0 + wm + mt * 16 + (lane >> 2);
#pragma unroll
        for (int nt = 0; nt < 8; nt++) {
            int col = n0 + wn + nt * 8 + 2 * (lane & 3);
            float b0 = bias[col], b1 = bias[col + 1];
            float v0 = acc[mt][nt][0] + b0, v1 = acc[mt][nt][1] + b1;
            float v2 = acc[mt][nt][2] + b0, v3 = acc[mt][nt][3] + b1;
            size_t off0 = (size_t)row * DD + col;
            size_t off1 = (size_t)(row + 8) * DD + col;
            if (mode == 0) {
                *(float2*)(C + off0) = make_float2(v0, v1);
                *(float2*)(C + off1) = make_float2(v2, v3);
            } else {
                v0 *= sc; v1 *= sc; v2 *= sc; v3 *= sc;
                *(__half2*)(o16 + off0) = __floats2half2_rn(v0, v1);
                *(__half2*)(o16 + off1) = __floats2half2_rn(v2, v3);
            }
        }
    }
}

__global__ __launch_bounds__(128, 3)
void gemm_qkv_tc(const float* __restrict__ bq, const float* __restrict__ bk,
                 const float* __restrict__ bv)
{
    const int z = blockIdx.z;
    if (z == 0)
        gemm_tc_body(g_x16, g_wt16[0], bq, nullptr, 1, g_q16);
    else if (z == 1)
        gemm_tc_body(g_x16, g_wt16[1], bk, nullptr, 2, g_k16);
    else
        gemm_tc_body(g_x16, g_wt16[2], bv, nullptr, 2, g_v16);
}

__global__ __launch_bounds__(128, 3)
void gemm_out_tc(const float* __restrict__ bo, float* __restrict__ out)
{
    gemm_tc_body(g_ao16, g_wt16[3], bo, out, 0, nullptr);
}

// ---------------------------------------------------------------------------
// Tensor-core flash attention, causal, single-pass fp16.
// CTA: 64 q rows, 128 threads, 2-stage cp.async K/V pipeline, 4 CTAs/SM.
// Row-sum l computed in fp32 from the f16 P registers (no ones column).
// ---------------------------------------------------------------------------
#define VPITCH 88
#define AQ 0
#define AST 8192
#define SK 0
#define SV 8192
#define ASTAGE (8192 + 64 * VPITCH * 2)     // 19456
#define ATT_SMEM (AST + 2 * ASTAGE)         // 47104

__device__ __forceinline__ void attn_load_stage(uint32_t sb, int stage,
                                                const __half* gk,
                                                const __half* gv,
                                                int k0, int tid)
{
    uint32_t so = sb + AST + stage * ASTAGE;
#pragma unroll
    for (int i = 0; i < 4; i++) {
        int idx = tid + (i << 7);
        int r = idx >> 3, c = idx & 7;
        uint32_t offk = 128u * r + 16u * (c ^ (r & 7));
        size_t g = (size_t)(k0 + r) * DD + c * 8;
        cpasync16(so + SK + offk, gk + g);
        uint32_t offv = (uint32_t)(r * VPITCH + c * 8) * 2;
        cpasync16(so + SV + offv, gv + g);
    }
}

__global__ __launch_bounds__(128, 4) void attn_tc_kernel()
{
    extern __shared__ char sm[];
    const uint32_t sb = smem_to_u32(sm);
    const int tid = threadIdx.x;
    const int lane = tid & 31;
    const int wid = tid >> 5;
    const int bh = blockIdx.y;
    const int b = bh >> 4;
    const int h = bh & 15;
    const int q0 = (int)(gridDim.x - 1 - blockIdx.x) * 64;   // big tiles first

    const size_t tok0 = (size_t)(b * LL);
    const __half* gq = g_q16 + (tok0 + q0) * DD + h * 64;
    const __half* gk = g_k16 + tok0 * DD + h * 64;
    const __half* gv = g_v16 + tok0 * DD + h * 64;

    // kick off stage 0 loads immediately
    attn_load_stage(sb, 0, gk, gv, 0, tid);
    cpcommit();

    // Load Q tile (swizzled, regular loads)
#pragma unroll
    for (int i = 0; i < 4; i++) {
        int idx = tid + (i << 7);
        int r = idx >> 3, c = idx & 7;
        uint32_t off = 128u * r + 16u * (c ^ (r & 7));
        *(uint4*)(sm + AQ + off) = *(const uint4*)(gq + (size_t)r * DD + c * 8);
    }

    const int arow = 16 * wid + (lane & 15);
    const int ac = lane >> 4;
    const int asw = arow & 7;
    const int brow_in = ((lane >> 4) << 3) + (lane & 7);
    const int bc = (lane >> 3) & 1;
    const int bsw = brow_in & 7;
    const int vrow_in = (lane & 7) + ((lane >> 3) & 1) * 8;
    const int vnc = (lane >> 4);

    float oacc[8][4];
#pragma unroll
    for (int i = 0; i < 8; i++)
#pragma unroll
        for (int j = 0; j < 4; j++) oacc[i][j] = 0.f;
    float m2[2] = {-1e30f, -1e30f};
    float l0 = 0.f, l1 = 0.f;

    const int nk = (q0 >> 6) + 1;
    for (int kt = 0; kt < nk; kt++) {
        if (kt + 1 < nk) {
            attn_load_stage(sb, (kt + 1) & 1, gk, gv, (kt + 1) * 64, tid);
            cpcommit();
            cpwait<1>();
        } else {
            cpwait<0>();
        }
        __syncthreads();
        const uint32_t st = sb + AST + (kt & 1) * ASTAGE;

        // ---- S = Q K^T (single-pass fp16), 16x64 per warp ----
        float sacc[8][4];
#pragma unroll
        for (int i = 0; i < 8; i++)
#pragma unroll
            for (int j = 0; j < 4; j++) sacc[i][j] = 0.f;

#pragma unroll
        for (int ks = 0; ks < 4; ks++) {
            uint32_t qf[4], kf[4][4];
            uint32_t ca = 16u * (uint32_t)((2 * ks + ac) ^ asw);
            ldsm4(qf, sb + AQ + 128u * arow + ca);
            uint32_t cb = 16u * (uint32_t)((2 * ks + bc) ^ bsw);
#pragma unroll
            for (int np = 0; np < 4; np++)
                ldsm4(kf[np], st + SK + 128u * (16 * np + brow_in) + cb);
#pragma unroll
            for (int nt = 0; nt < 8; nt++)
                mma_f16(sacc[nt], qf, &kf[nt >> 1][(nt & 1) * 2]);
        }

        // ---- causal mask (diagonal tile only) ----
        if (kt == nk - 1) {
            const int r0g = 16 * wid + (lane >> 2);
#pragma unroll
            for (int nt = 0; nt < 8; nt++) {
                int kc = 8 * nt + 2 * (lane & 3);
                if (kc > r0g)     sacc[nt][0] = -1e30f;
                if (kc + 1 > r0g) sacc[nt][1] = -1e30f;
                if (kc > r0g + 8)     sacc[nt][2] = -1e30f;
                if (kc + 1 > r0g + 8) sacc[nt][3] = -1e30f;
            }
        }

        // ---- online softmax (log2 domain), P in f16x2 ----
        float mx0 = -1e30f, mx1 = -1e30f;
#pragma unroll
        for (int nt = 0; nt < 8; nt++) {
            mx0 = fmaxf(mx0, fmaxf(sacc[nt][0], sacc[nt][1]));
            mx1 = fmaxf(mx1, fmaxf(sacc[nt][2], sacc[nt][3]));
        }
        mx0 = fmaxf(mx0, __shfl_xor_sync(0xffffffffu, mx0, 1));
        mx0 = fmaxf(mx0, __shfl_xor_sync(0xffffffffu, mx0, 2));
        mx1 = fmaxf(mx1, __shfl_xor_sync(0xffffffffu, mx1, 1));
        mx1 = fmaxf(mx1, __shfl_xor_sync(0xffffffffu, mx1, 2));
        float m2n0 = fmaxf(m2[0], mx0 * L2E);
        float m2n1 = fmaxf(m2[1], mx1 * L2E);
        float al0 = exp2f(m2[0] - m2n0);
        float al1 = exp2f(m2[1] - m2n1);
        m2[0] = m2n0; m2[1] = m2n1;

        uint32_t pf[4][4];
#pragma unroll
        for (int ks = 0; ks < 4; ks++) {
            pf[ks][0] = ex2_f16x2(cvt_f16x2(fmaf(sacc[2*ks][1],   L2E, -m2n0),
                                            fmaf(sacc[2*ks][0],   L2E, -m2n0)));
            pf[ks][1] = ex2_f16x2(cvt_f16x2(fmaf(sacc[2*ks][3],   L2E, -m2n1),
                                            fmaf(sacc[2*ks][2],   L2E, -m2n1)));
            pf[ks][2] = ex2_f16x2(cvt_f16x2(fmaf(sacc[2*ks+1][1], L2E, -m2n0),
                                            fmaf(sacc[2*ks+1][0], L2E, -m2n0)));
            pf[ks][3] = ex2_f16x2(cvt_f16x2(fmaf(sacc[2*ks+1][3], L2E, -m2n1),
                                            fmaf(sacc[2*ks+1][2], L2E, -m2n1)));
        }

        // ---- row-sum l from the same f16 P values (replaces ones column) ----
        float rs0 = 0.f, rs1 = 0.f;
#pragma unroll
        for (int ks = 0; ks < 4; ks++) {
            float2 a0 = __half22float2(*(const __half2*)&pf[ks][0]);
            float2 a2 = __half22float2(*(const __half2*)&pf[ks][2]);
            float2 a1 = __half22float2(*(const __half2*)&pf[ks][1]);
            float2 a3 = __half22float2(*(const __half2*)&pf[ks][3]);
            rs0 += (a0.x + a0.y) + (a2.x + a2.y);
            rs1 += (a1.x + a1.y) + (a3.x + a3.y);
        }
        rs0 += __shfl_xor_sync(0xffffffffu, rs0, 1);
        rs0 += __shfl_xor_sync(0xffffffffu, rs0, 2);
        rs1 += __shfl_xor_sync(0xffffffffu, rs1, 1);
        rs1 += __shfl_xor_sync(0xffffffffu, rs1, 2);
        l0 = l0 * al0 + rs0;
        l1 = l1 * al1 + rs1;

#pragma unroll
        for (int nt = 0; nt < 8; nt++) {
            oacc[nt][0] *= al0; oacc[nt][1] *= al0;
            oacc[nt][2] *= al1; oacc[nt][3] *= al1;
        }

        // ---- O += P @ V (single-pass fp16, 64 cols) ----
#pragma unroll
        for (int ks = 0; ks < 4; ks++) {
            const uint32_t vrow = (uint32_t)(16 * ks + vrow_in) * (VPITCH * 2);
#pragma unroll
            for (int np = 0; np < 4; np++) {
                uint32_t vf[4];
                uint32_t voff = vrow + 16u * (uint32_t)(2 * np + vnc);
                ldsm4t(vf, st + SV + voff);
                mma_f16(oacc[2 * np], pf[ks], &vf[0]);
                mma_f16(oacc[2 * np + 1], pf[ks], &vf[2]);
            }
        }
        __syncthreads();
    }

    // ---- normalize and store fp16 (out-proj operand) ----
    float i0 = 1.0f / l0;
    float i1 = 1.0f / l1;
    const int row0 = q0 + 16 * wid + (lane >> 2);
    __half* base16 = g_ao16 + tok0 * DD + h * 64;
#pragma unroll
    for (int nt = 0; nt < 8; nt++) {
        int col = 8 * nt + 2 * (lane & 3);
        size_t off0 = (size_t)row0 * DD + col;
        size_t off1 = (size_t)(row0 + 8) * DD + col;
        *(__half2*)(base16 + off0) = __floats2half2_rn(oacc[nt][0] * i0, oacc[nt][1] * i0);
        *(__half2*)(base16 + off1) = __floats2half2_rn(oacc[nt][2] * i1, oacc[nt][3] * i1);
    }
}

// ---------------------------------------------------------------------------
extern "C" void kernel_launch(void* const* d_in, const int* in_sizes, int n_in,
                              void* d_out, int out_size)
{
    (void)in_sizes; (void)n_in; (void)out_size;
    const float* x  = (const float*)d_in[0];
    const float* wq = (const float*)d_in[2];
    const float* bq = (const float*)d_in[3];
    const float* wk = (const float*)d_in[4];
    const float* bk = (const float*)d_in[5];
    const float* wv = (const float*)d_in[6];
    const float* bv = (const float*)d_in[7];
    const float* wo = (const float*)d_in[8];
    const float* bo = (const float*)d_in[9];
    float* out = (float*)d_out;

    cudaFuncSetAttribute(gemm_qkv_tc, cudaFuncAttributeMaxDynamicSharedMemorySize,
                         GEMM_SMEM_BYTES);
    cudaFuncSetAttribute(gemm_out_tc, cudaFuncAttributeMaxDynamicSharedMemorySize,
                         GEMM_SMEM_BYTES);
    cudaFuncSetAttribute(attn_tc_kernel, cudaFuncAttributeMaxDynamicSharedMemorySize,
                         ATT_SMEM);

    xconv_kernel<<<(MM * DD / 4) / 256, 256>>>(x);
    wconv_kernel<<<dim3(32, 32, 4), dim3(32, 32)>>>(wq, wk, wv, wo);
    gemm_qkv_tc<<<dim3(DD / 128, MM / 128, 3), 128, GEMM_SMEM_BYTES>>>(bq, bk, bv);
    attn_tc_kernel<<<dim3(LL / 64, BB * HH), 128, ATT_SMEM>>>();
    gemm_out_tc<<<dim3(DD / 128, MM / 128), 128, GEMM_SMEM_BYTES>>>(bo, out);
}

// round 15
// speedup vs baseline: 1.0502x; 1.0385x over previous
#include <cuda_runtime.h>
#include <cuda_bf16.h>
#include <cuda_fp16.h>
#include <cstdint>
#include <math.h>

#define BB 2
#define LL 2048
#define DD 1024
#define HH 16
#define DHH 64
#define MM (BB * LL)   // 4096
#define L2E 1.4426950408889634f

// ---------------------------------------------------------------------------
// Scratch (__device__ globals: allocation-free rule)
// ---------------------------------------------------------------------------
__device__ __half g_x16[MM * DD];        // x in fp16
__device__ __half g_ao16[MM * DD];       // attention output in fp16
__device__ __half g_wt16[4][DD * DD];    // transposed weights [which][n][k] fp16

__device__ __half g_q16[MM * DD];        // Q fp16, pre-scaled by 0.125
__device__ __half g_k16[MM * DD];        // K fp16
__device__ __half g_v16[MM * DD];        // V fp16

// ---------------------------------------------------------------------------
// PTX helpers (portable sm_80+ subset; plain sm_103 target — no tcgen05)
// ---------------------------------------------------------------------------
__device__ __forceinline__ uint32_t smem_to_u32(const void* p) {
    uint32_t a;
    asm("{ .reg .u64 t; cvta.to.shared.u64 t, %1; cvt.u32.u64 %0, t; }"
        : "=r"(a) : "l"(p));
    return a;
}
__device__ __forceinline__ void cpasync16(uint32_t s, const void* g) {
    asm volatile("cp.async.cg.shared.global [%0], [%1], 16;" :: "r"(s), "l"(g));
}
__device__ __forceinline__ void cpcommit() {
    asm volatile("cp.async.commit_group;" ::: "memory");
}
template <int N>
__device__ __forceinline__ void cpwait() {
    asm volatile("cp.async.wait_group %0;" :: "n"(N) : "memory");
}
__device__ __forceinline__ void ldsm4(uint32_t* r, uint32_t addr) {
    asm volatile("ldmatrix.sync.aligned.m8n8.x4.shared.b16 {%0,%1,%2,%3}, [%4];"
                 : "=r"(r[0]), "=r"(r[1]), "=r"(r[2]), "=r"(r[3]) : "r"(addr));
}
__device__ __forceinline__ void ldsm4t(uint32_t* r, uint32_t addr) {
    asm volatile("ldmatrix.sync.aligned.m8n8.x4.trans.shared.b16 {%0,%1,%2,%3}, [%4];"
                 : "=r"(r[0]), "=r"(r[1]), "=r"(r[2]), "=r"(r[3]) : "r"(addr));
}
__device__ __forceinline__ void mma_f16(float* d, const uint32_t* a, const uint32_t* b) {
    asm volatile(
        "mma.sync.aligned.m16n8k16.row.col.f32.f16.f16.f32 "
        "{%0,%1,%2,%3}, {%4,%5,%6,%7}, {%8,%9}, {%0,%1,%2,%3};"
        : "+f"(d[0]), "+f"(d[1]), "+f"(d[2]), "+f"(d[3])
        : "r"(a[0]), "r"(a[1]), "r"(a[2]), "r"(a[3]), "r"(b[0]), "r"(b[1]));
}
__device__ __forceinline__ uint32_t cvt_f16x2(float hi, float lo) {
    uint32_t r;
    asm volatile("cvt.rn.f16x2.f32 %0, %1, %2;" : "=r"(r) : "f"(hi), "f"(lo));
    return r;
}
__device__ __forceinline__ uint32_t ex2_f16x2(uint32_t x) {
    uint32_t r;
    asm volatile("ex2.approx.f16x2 %0, %1;" : "=r"(r) : "r"(x));
    return r;
}

// ---------------------------------------------------------------------------
// Merged prep kernel: z=0..3 -> weight transpose+convert; z=4 -> x convert.
// ---------------------------------------------------------------------------
__global__ __launch_bounds__(1024) void prep_kernel(const float* __restrict__ x,
                                                    const float* __restrict__ wq,
                                                    const float* __restrict__ wk,
                                                    const float* __restrict__ wv,
                                                    const float* __restrict__ wo)
{
    int which = blockIdx.z;
    if (which == 4) {
        // x: fp32 -> fp16, 1M float4s over 1024 blocks x 1024 threads
        int i = (blockIdx.y * 32 + blockIdx.x) * 1024 + threadIdx.y * 32 + threadIdx.x;
        float4 v = ((const float4*)x)[i];
        __half2* hp = (__half2*)g_x16;
        hp[2 * i]     = __floats2half2_rn(v.x, v.y);
        hp[2 * i + 1] = __floats2half2_rn(v.z, v.w);
        return;
    }
    __shared__ float t[32][33];
    const float* w = (which == 0) ? wq : (which == 1) ? wk : (which == 2) ? wv : wo;
    int kk = blockIdx.y * 32 + threadIdx.y;
    int nn = blockIdx.x * 32 + threadIdx.x;
    t[threadIdx.y][threadIdx.x] = w[kk * DD + nn];
    __syncthreads();
    int on = blockIdx.x * 32 + threadIdx.y;
    int ok = blockIdx.y * 32 + threadIdx.x;
    g_wt16[which][on * DD + ok] = __float2half_rn(t[threadIdx.x][threadIdx.y]);
}

// ---------------------------------------------------------------------------
// Single-pass fp16 HMMA GEMM (R12 config): C[128,128 tile] = A @ Wt^T + bias
// 128 threads, warp grid 2(m)x2(n), warp tile 64x64, BK=64, 2-stage cp.async,
// 3 CTAs/SM.
// mode 0: fp32 out; mode 1: fp16 out *0.125 (Q); mode 2: fp16 out (K/V)
// ---------------------------------------------------------------------------
#define BK 64
#define APITCH 72
#define BUF_BYTES (128 * APITCH * 2)        // 18432 per operand buffer
#define GEMM_STAGE (2 * BUF_BYTES)          // 36864 (A + B)
#define GEMM_SMEM_BYTES (2 * GEMM_STAGE)    // 73728 -> 3 CTAs/SM

__device__ __forceinline__ void load_stage(uint32_t sbase, int stage,
                                           const __half* __restrict__ A,
                                           const __half* __restrict__ B,
                                           int m0, int n0, int k0, int tid)
{
    uint32_t so = sbase + stage * GEMM_STAGE;
#pragma unroll
    for (int j = 0; j < 8; j++) {
        int c = tid + (j << 7);                 // 0..1023
        int row = c >> 3;                       // 0..127
        int col = (c & 7) << 3;                 // 0..56
        uint32_t soff = (uint32_t)(row * APITCH + col) * 2;
        cpasync16(so + 0 * BUF_BYTES + soff, A + (size_t)(m0 + row) * DD + k0 + col);
        cpasync16(so + 1 * BUF_BYTES + soff, B + (size_t)(n0 + row) * DD + k0 + col);
    }
}

__device__ __forceinline__ void gemm_tc_body(const __half* __restrict__ A,
                                             const __half* __restrict__ B,
                                             const float* __restrict__ bias,
                                             float* __restrict__ C,
                                             int mode, __half* o16)
{
    extern __shared__ char smem[];
    const uint32_t sbase = smem_to_u32(smem);

    const int tid = threadIdx.x;
    const int lane = tid & 31;
    const int wid = tid >> 5;           // 0..3
    const int wm = (wid >> 1) * 64;     // 0 or 64
    const int wn = (wid & 1) * 64;      // 0 or 64
    const int m0 = blockIdx.y * 128;
    const int n0 = blockIdx.x * 128;

    const int a_row = wm + (lane & 15);
    const int a_col = (lane >> 4) << 3;
    const int b_row = wn + ((lane >> 4) << 3) + (lane & 7);
    const int b_col = ((lane >> 3) & 1) << 3;

    float acc[4][8][4];
#pragma unroll
    for (int i = 0; i < 4; i++)
#pragma unroll
        for (int j = 0; j < 8; j++)
#pragma unroll
            for (int r = 0; r < 4; r++) acc[i][j][r] = 0.f;

    load_stage(sbase, 0, A, B, m0, n0, 0, tid);
    cpcommit();
    load_stage(sbase, 1, A, B, m0, n0, BK, tid);
    cpcommit();

    const int NT = DD / BK;             // 16
    for (int kt = 0; kt < NT; kt++) {
        if (kt + 2 < NT) {
            cpwait<1>();
        } else {
            cpwait<0>();
        }
        __syncthreads();

        const uint32_t st = sbase + (kt & 1) * GEMM_STAGE;
#pragma unroll
        for (int ks = 0; ks < 4; ks++) {
            const int kofs = ks * 16;
            uint32_t ah[4][4], bh[4][4];
#pragma unroll
            for (int mt = 0; mt < 4; mt++) {
                uint32_t off = (uint32_t)((a_row + mt * 16) * APITCH + kofs + a_col) * 2;
                ldsm4(ah[mt], st + 0 * BUF_BYTES + off);
            }
#pragma unroll
            for (int nt2 = 0; nt2 < 4; nt2++) {
                uint32_t off = (uint32_t)((b_row + nt2 * 16) * APITCH + kofs + b_col) * 2;
                ldsm4(bh[nt2], st + 1 * BUF_BYTES + off);
            }
#pragma unroll
            for (int mt = 0; mt < 4; mt++)
#pragma unroll
                for (int nt = 0; nt < 8; nt++)
                    mma_f16(acc[mt][nt], ah[mt], &bh[nt >> 1][(nt & 1) * 2]);
        }
        __syncthreads();
        if (kt + 2 < NT) {
            load_stage(sbase, kt & 1, A, B, m0, n0, (kt + 2) * BK, tid);
            cpcommit();
        }
    }

    const float sc = (mode == 1) ? 0.125f : 1.0f;
#pragma unroll
    for (int mt = 0; mt < 4; mt++) {
        int row = m0 + wm + mt * 16 + (lane >> 2);
#pragma unroll
        for (int nt = 0; nt < 8; nt++) {
            int col = n0 + wn + nt * 8 + 2 * (lane & 3);
            float b0 = bias[col], b1 = bias[col + 1];
            float v0 = acc[mt][nt][0] + b0, v1 = acc[mt][nt][1] + b1;
            float v2 = acc[mt][nt][2] + b0, v3 = acc[mt][nt][3] + b1;
            size_t off0 = (size_t)row * DD + col;
            size_t off1 = (size_t)(row + 8) * DD + col;
            if (mode == 0) {
                *(float2*)(C + off0) = make_float2(v0, v1);
                *(float2*)(C + off1) = make_float2(v2, v3);
            } else {
                v0 *= sc; v1 *= sc; v2 *= sc; v3 *= sc;
                *(__half2*)(o16 + off0) = __floats2half2_rn(v0, v1);
                *(__half2*)(o16 + off1) = __floats2half2_rn(v2, v3);
            }
        }
    }
}

__global__ __launch_bounds__(128, 3)
void gemm_qkv_tc(const float* __restrict__ bq, const float* __restrict__ bk,
                 const float* __restrict__ bv)
{
    const int z = blockIdx.z;
    if (z == 0)
        gemm_tc_body(g_x16, g_wt16[0], bq, nullptr, 1, g_q16);
    else if (z == 1)
        gemm_tc_body(g_x16, g_wt16[1], bk, nullptr, 2, g_k16);
    else
        gemm_tc_body(g_x16, g_wt16[2], bv, nullptr, 2, g_v16);
}

__global__ __launch_bounds__(128, 3)
void gemm_out_tc(const float* __restrict__ bo, float* __restrict__ out)
{
    gemm_tc_body(g_ao16, g_wt16[3], bo, out, 0, nullptr);
}

// ---------------------------------------------------------------------------
// Tensor-core flash attention, causal, single-pass fp16.  (R12 version)
// CTA: 64 q rows, 128 threads, 2-stage cp.async K/V pipeline, 4 CTAs/SM.
// Ones-column in V col 64 carries the row-sum l through the PV MMA.
// ---------------------------------------------------------------------------
#define VPITCH 88
#define AQ 0
#define AST 8192
#define SK 0
#define SV 8192
#define ASTAGE (8192 + 64 * VPITCH * 2)     // 19456
#define ATT_SMEM (AST + 2 * ASTAGE)         // 47104

__device__ __forceinline__ void attn_load_stage(uint32_t sb, int stage,
                                                const __half* gk,
                                                const __half* gv,
                                                int k0, int tid)
{
    uint32_t so = sb + AST + stage * ASTAGE;
#pragma unroll
    for (int i = 0; i < 4; i++) {
        int idx = tid + (i << 7);
        int r = idx >> 3, c = idx & 7;
        uint32_t offk = 128u * r + 16u * (c ^ (r & 7));
        size_t g = (size_t)(k0 + r) * DD + c * 8;
        cpasync16(so + SK + offk, gk + g);
        uint32_t offv = (uint32_t)(r * VPITCH + c * 8) * 2;
        cpasync16(so + SV + offv, gv + g);
    }
}

__global__ __launch_bounds__(128, 4) void attn_tc_kernel()
{
    extern __shared__ char sm[];
    const uint32_t sb = smem_to_u32(sm);
    const int tid = threadIdx.x;
    const int lane = tid & 31;
    const int wid = tid >> 5;
    const int bh = blockIdx.y;
    const int b = bh >> 4;
    const int h = bh & 15;
    const int q0 = (int)(gridDim.x - 1 - blockIdx.x) * 64;   // big tiles first

    const size_t tok0 = (size_t)(b * LL);
    const __half* gq = g_q16 + (tok0 + q0) * DD + h * 64;
    const __half* gk = g_k16 + tok0 * DD + h * 64;
    const __half* gv = g_v16 + tok0 * DD + h * 64;

    // kick off stage 0 loads immediately
    attn_load_stage(sb, 0, gk, gv, 0, tid);
    cpcommit();

    // V pad cols 64..87 in BOTH stages: zeros
#pragma unroll
    for (int s = 0; s < 2; s++) {
        char* vb = sm + AST + s * ASTAGE;
        for (int i = tid; i < 64 * 3; i += 128) {
            int r = i / 3, c = i % 3;
            uint32_t off = (uint32_t)(r * VPITCH + 64 + 8 * c) * 2;
            *(uint4*)(vb + SV + off) = make_uint4(0, 0, 0, 0);
        }
    }
    __syncthreads();   // zero-fill visible before ones-column write
#pragma unroll
    for (int s = 0; s < 2; s++) {
        char* vb = sm + AST + s * ASTAGE;
        if (tid < 64) ((__half*)(vb + SV))[tid * VPITCH + 64] = __float2half(1.0f);
    }

    // Load Q tile (swizzled, regular loads)
#pragma unroll
    for (int i = 0; i < 4; i++) {
        int idx = tid + (i << 7);
        int r = idx >> 3, c = idx & 7;
        uint32_t off = 128u * r + 16u * (c ^ (r & 7));
        *(uint4*)(sm + AQ + off) = *(const uint4*)(gq + (size_t)r * DD + c * 8);
    }

    const int arow = 16 * wid + (lane & 15);
    const int ac = lane >> 4;
    const int asw = arow & 7;
    const int brow_in = ((lane >> 4) << 3) + (lane & 7);
    const int bc = (lane >> 3) & 1;
    const int bsw = brow_in & 7;
    const int vrow_in = (lane & 7) + ((lane >> 3) & 1) * 8;
    const int vnc = (lane >> 4);

    float oacc[9][4];
#pragma unroll
    for (int i = 0; i < 9; i++)
#pragma unroll
        for (int j = 0; j < 4; j++) oacc[i][j] = 0.f;
    float m2[2] = {-1e30f, -1e30f};

    const int nk = (q0 >> 6) + 1;
    for (int kt = 0; kt < nk; kt++) {
        if (kt + 1 < nk) {
            attn_load_stage(sb, (kt + 1) & 1, gk, gv, (kt + 1) * 64, tid);
            cpcommit();
            cpwait<1>();
        } else {
            cpwait<0>();
        }
        __syncthreads();
        const uint32_t st = sb + AST + (kt & 1) * ASTAGE;

        // ---- S = Q K^T (single-pass fp16), 16x64 per warp ----
        float sacc[8][4];
#pragma unroll
        for (int i = 0; i < 8; i++)
#pragma unroll
            for (int j = 0; j < 4; j++) sacc[i][j] = 0.f;

#pragma unroll
        for (int ks = 0; ks < 4; ks++) {
            uint32_t qf[4], kf[4][4];
            uint32_t ca = 16u * (uint32_t)((2 * ks + ac) ^ asw);
            ldsm4(qf, sb + AQ + 128u * arow + ca);
            uint32_t cb = 16u * (uint32_t)((2 * ks + bc) ^ bsw);
#pragma unroll
            for (int np = 0; np < 4; np++)
                ldsm4(kf[np], st + SK + 128u * (16 * np + brow_in) + cb);
#pragma unroll
            for (int nt = 0; nt < 8; nt++)
                mma_f16(sacc[nt], qf, &kf[nt >> 1][(nt & 1) * 2]);
        }

        // ---- causal mask (diagonal tile only) ----
        if (kt == nk - 1) {
            const int r0g = 16 * wid + (lane >> 2);
#pragma unroll
            for (int nt = 0; nt < 8; nt++) {
                int kc = 8 * nt + 2 * (lane & 3);
                if (kc > r0g)     sacc[nt][0] = -1e30f;
                if (kc + 1 > r0g) sacc[nt][1] = -1e30f;
                if (kc > r0g + 8)     sacc[nt][2] = -1e30f;
                if (kc + 1 > r0g + 8) sacc[nt][3] = -1e30f;
            }
        }

        // ---- online softmax (log2 domain), P in f16x2 ----
        float mx0 = -1e30f, mx1 = -1e30f;
#pragma unroll
        for (int nt = 0; nt < 8; nt++) {
            mx0 = fmaxf(mx0, fmaxf(sacc[nt][0], sacc[nt][1]));
            mx1 = fmaxf(mx1, fmaxf(sacc[nt][2], sacc[nt][3]));
        }
        mx0 = fmaxf(mx0, __shfl_xor_sync(0xffffffffu, mx0, 1));
        mx0 = fmaxf(mx0, __shfl_xor_sync(0xffffffffu, mx0, 2));
        mx1 = fmaxf(mx1, __shfl_xor_sync(0xffffffffu, mx1, 1));
        mx1 = fmaxf(mx1, __shfl_xor_sync(0xffffffffu, mx1, 2));
        float m2n0 = fmaxf(m2[0], mx0 * L2E);
        float m2n1 = fmaxf(m2[1], mx1 * L2E);
        float al0 = exp2f(m2[0] - m2n0);
        float al1 = exp2f(m2[1] - m2n1);
        m2[0] = m2n0; m2[1] = m2n1;

        uint32_t pf[4][4];
#pragma unroll
        for (int ks = 0; ks < 4; ks++) {
            pf[ks][0] = ex2_f16x2(cvt_f16x2(fmaf(sacc[2*ks][1],   L2E, -m2n0),
                                            fmaf(sacc[2*ks][0],   L2E, -m2n0)));
            pf[ks][1] = ex2_f16x2(cvt_f16x2(fmaf(sacc[2*ks][3],   L2E, -m2n1),
                                            fmaf(sacc[2*ks][2],   L2E, -m2n1)));
            pf[ks][2] = ex2_f16x2(cvt_f16x2(fmaf(sacc[2*ks+1][1], L2E, -m2n0),
                                            fmaf(sacc[2*ks+1][0], L2E, -m2n0)));
            pf[ks][3] = ex2_f16x2(cvt_f16x2(fmaf(sacc[2*ks+1][3], L2E, -m2n1),
                                            fmaf(sacc[2*ks+1][2], L2E, -m2n1)));
        }
#pragma unroll
        for (int nt = 0; nt < 9; nt++) {
            oacc[nt][0] *= al0; oacc[nt][1] *= al0;
            oacc[nt][2] *= al1; oacc[nt][3] *= al1;
        }

        // ---- O += P @ V (single-pass fp16; n=72 incl. ones column) ----
#pragma unroll
        for (int ks = 0; ks < 4; ks++) {
            const uint32_t vrow = (uint32_t)(16 * ks + vrow_in) * (VPITCH * 2);
#pragma unroll
            for (int np = 0; np < 5; np++) {
                uint32_t vf[4];
                uint32_t voff = vrow + 16u * (uint32_t)(2 * np + vnc);
                ldsm4t(vf, st + SV + voff);
                mma_f16(oacc[2 * np], pf[ks], &vf[0]);
                if (np < 4) mma_f16(oacc[2 * np + 1], pf[ks], &vf[2]);
            }
        }
        __syncthreads();
    }

    // ---- normalize and store fp16 (out-proj operand) ----
    const int src = lane & ~3;
    float l0 = __shfl_sync(0xffffffffu, oacc[8][0], src);
    float l1 = __shfl_sync(0xffffffffu, oacc[8][2], src);
    float i0 = 1.0f / l0;
    float i1 = 1.0f / l1;
    const int row0 = q0 + 16 * wid + (lane >> 2);
    __half* base16 = g_ao16 + tok0 * DD + h * 64;
#pragma unroll
    for (int nt = 0; nt < 8; nt++) {
        int col = 8 * nt + 2 * (lane & 3);
        size_t off0 = (size_t)row0 * DD + col;
        size_t off1 = (size_t)(row0 + 8) * DD + col;
        *(__half2*)(base16 + off0) = __floats2half2_rn(oacc[nt][0] * i0, oacc[nt][1] * i0);
        *(__half2*)(base16 + off1) = __floats2half2_rn(oacc[nt][2] * i1, oacc[nt][3] * i1);
    }
}

// ---------------------------------------------------------------------------
extern "C" void kernel_launch(void* const* d_in, const int* in_sizes, int n_in,
                              void* d_out, int out_size)
{
    (void)in_sizes; (void)n_in; (void)out_size;
    const float* x  = (const float*)d_in[0];
    const float* wq = (const float*)d_in[2];
    const float* bq = (const float*)d_in[3];
    const float* wk = (const float*)d_in[4];
    const float* bk = (const float*)d_in[5];
    const float* wv = (const float*)d_in[6];
    const float* bv = (const float*)d_in[7];
    const float* wo = (const float*)d_in[8];
    const float* bo = (const float*)d_in[9];
    float* out = (float*)d_out;

    cudaFuncSetAttribute(gemm_qkv_tc, cudaFuncAttributeMaxDynamicSharedMemorySize,
                         GEMM_SMEM_BYTES);
    cudaFuncSetAttribute(gemm_out_tc, cudaFuncAttributeMaxDynamicSharedMemorySize,
                         GEMM_SMEM_BYTES);
    cudaFuncSetAttribute(attn_tc_kernel, cudaFuncAttributeMaxDynamicSharedMemorySize,
                         ATT_SMEM);

    prep_kernel<<<dim3(32, 32, 5), dim3(32, 32)>>>(x, wq, wk, wv, wo);
    gemm_qkv_tc<<<dim3(DD / 128, MM / 128, 3), 128, GEMM_SMEM_BYTES>>>(bq, bk, bv);
    attn_tc_kernel<<<dim3(LL / 64, BB * HH), 128, ATT_SMEM>>>();
    gemm_out_tc<<<dim3(DD / 128, MM / 128), 128, GEMM_SMEM_BYTES>>>(bo, out);
}

// round 16
// speedup vs baseline: 1.0508x; 1.0006x over previous
#include <cuda_runtime.h>
#include <cuda_bf16.h>
#include <cuda_fp16.h>
#include <cstdint>
#include <math.h>

#define BB 2
#define LL 2048
#define DD 1024
#define HH 16
#define DHH 64
#define MM (BB * LL)   // 4096
#define L2E 1.4426950408889634f

// ---------------------------------------------------------------------------
// Scratch (__device__ globals: allocation-free rule)
// ---------------------------------------------------------------------------
__device__ __half g_x16[MM * DD];        // x in fp16
__device__ __half g_ao16[MM * DD];       // attention output in fp16
__device__ __half g_wt16[4][DD * DD];    // transposed weights [which][n][k] fp16

__device__ __half g_q16[MM * DD];        // Q fp16, pre-scaled by 0.125
__device__ __half g_k16[MM * DD];        // K fp16
__device__ __half g_v16[MM * DD];        // V fp16

// ---------------------------------------------------------------------------
// PTX helpers (portable sm_80+ subset; plain sm_103 target — no tcgen05)
// ---------------------------------------------------------------------------
__device__ __forceinline__ uint32_t smem_to_u32(const void* p) {
    uint32_t a;
    asm("{ .reg .u64 t; cvta.to.shared.u64 t, %1; cvt.u32.u64 %0, t; }"
        : "=r"(a) : "l"(p));
    return a;
}
__device__ __forceinline__ void cpasync16(uint32_t s, const void* g) {
    asm volatile("cp.async.cg.shared.global [%0], [%1], 16;" :: "r"(s), "l"(g));
}
__device__ __forceinline__ void cpcommit() {
    asm volatile("cp.async.commit_group;" ::: "memory");
}
template <int N>
__device__ __forceinline__ void cpwait() {
    asm volatile("cp.async.wait_group %0;" :: "n"(N) : "memory");
}
__device__ __forceinline__ void ldsm4(uint32_t* r, uint32_t addr) {
    asm volatile("ldmatrix.sync.aligned.m8n8.x4.shared.b16 {%0,%1,%2,%3}, [%4];"
                 : "=r"(r[0]), "=r"(r[1]), "=r"(r[2]), "=r"(r[3]) : "r"(addr));
}
__device__ __forceinline__ void ldsm4t(uint32_t* r, uint32_t addr) {
    asm volatile("ldmatrix.sync.aligned.m8n8.x4.trans.shared.b16 {%0,%1,%2,%3}, [%4];"
                 : "=r"(r[0]), "=r"(r[1]), "=r"(r[2]), "=r"(r[3]) : "r"(addr));
}
__device__ __forceinline__ void mma_f16(float* d, const uint32_t* a, const uint32_t* b) {
    asm volatile(
        "mma.sync.aligned.m16n8k16.row.col.f32.f16.f16.f32 "
        "{%0,%1,%2,%3}, {%4,%5,%6,%7}, {%8,%9}, {%0,%1,%2,%3};"
        : "+f"(d[0]), "+f"(d[1]), "+f"(d[2]), "+f"(d[3])
        : "r"(a[0]), "r"(a[1]), "r"(a[2]), "r"(a[3]), "r"(b[0]), "r"(b[1]));
}
__device__ __forceinline__ uint32_t cvt_f16x2(float hi, float lo) {
    uint32_t r;
    asm volatile("cvt.rn.f16x2.f32 %0, %1, %2;" : "=r"(r) : "f"(hi), "f"(lo));
    return r;
}
__device__ __forceinline__ uint32_t ex2_f16x2(uint32_t x) {
    uint32_t r;
    asm volatile("ex2.approx.f16x2 %0, %1;" : "=r"(r) : "r"(x));
    return r;
}

// ---------------------------------------------------------------------------
// Merged prep kernel: z=0..3 -> weight transpose+convert; z=4 -> x convert.
// ---------------------------------------------------------------------------
__global__ __launch_bounds__(1024) void prep_kernel(const float* __restrict__ x,
                                                    const float* __restrict__ wq,
                                                    const float* __restrict__ wk,
                                                    const float* __restrict__ wv,
                                                    const float* __restrict__ wo)
{
    int which = blockIdx.z;
    if (which == 4) {
        int i = (blockIdx.y * 32 + blockIdx.x) * 1024 + threadIdx.y * 32 + threadIdx.x;
        float4 v = ((const float4*)x)[i];
        __half2* hp = (__half2*)g_x16;
        hp[2 * i]     = __floats2half2_rn(v.x, v.y);
        hp[2 * i + 1] = __floats2half2_rn(v.z, v.w);
        return;
    }
    __shared__ float t[32][33];
    const float* w = (which == 0) ? wq : (which == 1) ? wk : (which == 2) ? wv : wo;
    int kk = blockIdx.y * 32 + threadIdx.y;
    int nn = blockIdx.x * 32 + threadIdx.x;
    t[threadIdx.y][threadIdx.x] = w[kk * DD + nn];
    __syncthreads();
    int on = blockIdx.x * 32 + threadIdx.y;
    int ok = blockIdx.y * 32 + threadIdx.x;
    g_wt16[which][on * DD + ok] = __float2half_rn(t[threadIdx.x][threadIdx.y]);
}

// ---------------------------------------------------------------------------
// qkv GEMM (R12/R15 config): 128x128 tile, warp tile 64x64, BK=64, 2-stage,
// 3 CTAs/SM.  mode 1: fp16 out *0.125 (Q); mode 2: fp16 out (K/V)
// ---------------------------------------------------------------------------
#define BK 64
#define APITCH 72
#define BUF_BYTES (128 * APITCH * 2)        // 18432 (128-row operand)
#define GEMM_STAGE (2 * BUF_BYTES)          // 36864 (A + B)
#define GEMM_SMEM_BYTES (2 * GEMM_STAGE)    // 73728 -> 3 CTAs/SM

__device__ __forceinline__ void load_stage(uint32_t sbase, int stage,
                                           const __half* __restrict__ A,
                                           const __half* __restrict__ B,
                                           int m0, int n0, int k0, int tid)
{
    uint32_t so = sbase + stage * GEMM_STAGE;
#pragma unroll
    for (int j = 0; j < 8; j++) {
        int c = tid + (j << 7);                 // 0..1023
        int row = c >> 3;                       // 0..127
        int col = (c & 7) << 3;                 // 0..56
        uint32_t soff = (uint32_t)(row * APITCH + col) * 2;
        cpasync16(so + 0 * BUF_BYTES + soff, A + (size_t)(m0 + row) * DD + k0 + col);
        cpasync16(so + 1 * BUF_BYTES + soff, B + (size_t)(n0 + row) * DD + k0 + col);
    }
}

__device__ __forceinline__ void gemm_tc_body(const __half* __restrict__ A,
                                             const __half* __restrict__ B,
                                             const float* __restrict__ bias,
                                             int mode, __half* o16)
{
    extern __shared__ char smem[];
    const uint32_t sbase = smem_to_u32(smem);

    const int tid = threadIdx.x;
    const int lane = tid & 31;
    const int wid = tid >> 5;           // 0..3
    const int wm = (wid >> 1) * 64;     // 0 or 64
    const int wn = (wid & 1) * 64;      // 0 or 64
    const int m0 = blockIdx.y * 128;
    const int n0 = blockIdx.x * 128;

    const int a_row = wm + (lane & 15);
    const int a_col = (lane >> 4) << 3;
    const int b_row = wn + ((lane >> 4) << 3) + (lane & 7);
    const int b_col = ((lane >> 3) & 1) << 3;

    float acc[4][8][4];
#pragma unroll
    for (int i = 0; i < 4; i++)
#pragma unroll
        for (int j = 0; j < 8; j++)
#pragma unroll
            for (int r = 0; r < 4; r++) acc[i][j][r] = 0.f;

    load_stage(sbase, 0, A, B, m0, n0, 0, tid);
    cpcommit();
    load_stage(sbase, 1, A, B, m0, n0, BK, tid);
    cpcommit();

    const int NT = DD / BK;             // 16
    for (int kt = 0; kt < NT; kt++) {
        if (kt + 2 < NT) {
            cpwait<1>();
        } else {
            cpwait<0>();
        }
        __syncthreads();

        const uint32_t st = sbase + (kt & 1) * GEMM_STAGE;
#pragma unroll
        for (int ks = 0; ks < 4; ks++) {
            const int kofs = ks * 16;
            uint32_t ah[4][4], bh[4][4];
#pragma unroll
            for (int mt = 0; mt < 4; mt++) {
                uint32_t off = (uint32_t)((a_row + mt * 16) * APITCH + kofs + a_col) * 2;
                ldsm4(ah[mt], st + 0 * BUF_BYTES + off);
            }
#pragma unroll
            for (int nt2 = 0; nt2 < 4; nt2++) {
                uint32_t off = (uint32_t)((b_row + nt2 * 16) * APITCH + kofs + b_col) * 2;
                ldsm4(bh[nt2], st + 1 * BUF_BYTES + off);
            }
#pragma unroll
            for (int mt = 0; mt < 4; mt++)
#pragma unroll
                for (int nt = 0; nt < 8; nt++)
                    mma_f16(acc[mt][nt], ah[mt], &bh[nt >> 1][(nt & 1) * 2]);
        }
        __syncthreads();
        if (kt + 2 < NT) {
            load_stage(sbase, kt & 1, A, B, m0, n0, (kt + 2) * BK, tid);
            cpcommit();
        }
    }

    const float sc = (mode == 1) ? 0.125f : 1.0f;
#pragma unroll
    for (int mt = 0; mt < 4; mt++) {
        int row = m0 + wm + mt * 16 + (lane >> 2);
#pragma unroll
        for (int nt = 0; nt < 8; nt++) {
            int col = n0 + wn + nt * 8 + 2 * (lane & 3);
            float b0 = bias[col], b1 = bias[col + 1];
            float v0 = (acc[mt][nt][0] + b0) * sc, v1 = (acc[mt][nt][1] + b1) * sc;
            float v2 = (acc[mt][nt][2] + b0) * sc, v3 = (acc[mt][nt][3] + b1) * sc;
            size_t off0 = (size_t)row * DD + col;
            size_t off1 = (size_t)(row + 8) * DD + col;
            *(__half2*)(o16 + off0) = __floats2half2_rn(v0, v1);
            *(__half2*)(o16 + off1) = __floats2half2_rn(v2, v3);
        }
    }
}

__global__ __launch_bounds__(128, 3)
void gemm_qkv_tc(const float* __restrict__ bq, const float* __restrict__ bk,
                 const float* __restrict__ bv)
{
    const int z = blockIdx.z;
    if (z == 0)
        gemm_tc_body(g_x16, g_wt16[0], bq, 1, g_q16);
    else if (z == 1)
        gemm_tc_body(g_x16, g_wt16[1], bk, 2, g_k16);
    else
        gemm_tc_body(g_x16, g_wt16[2], bv, 2, g_v16);
}

// ---------------------------------------------------------------------------
// out-proj GEMM: 128(M) x 64(N) CTA tile -> 512 CTAs; warp tile 64x32 (2x2),
// BK=64, 2-stage cp.async, 4 CTAs/SM.  fp32 output + bias.
// ---------------------------------------------------------------------------
#define OB_BYTES (64 * APITCH * 2)          // 9216 (64-row B operand)
#define OGEMM_STAGE (BUF_BYTES + OB_BYTES)  // 27648
#define OGEMM_SMEM_BYTES (2 * OGEMM_STAGE)  // 55296 -> 4 CTAs/SM

__device__ __forceinline__ void oload_stage(uint32_t sbase, int stage,
                                            const __half* __restrict__ A,
                                            const __half* __restrict__ B,
                                            int m0, int n0, int k0, int tid)
{
    uint32_t so = sbase + stage * OGEMM_STAGE;
#pragma unroll
    for (int j = 0; j < 8; j++) {
        int c = tid + (j << 7);                 // 0..1023
        int row = c >> 3;                       // 0..127
        int col = (c & 7) << 3;
        uint32_t soff = (uint32_t)(row * APITCH + col) * 2;
        cpasync16(so + soff, A + (size_t)(m0 + row) * DD + k0 + col);
    }
#pragma unroll
    for (int j = 0; j < 4; j++) {
        int c = tid + (j << 7);                 // 0..511
        int row = c >> 3;                       // 0..63
        int col = (c & 7) << 3;
        uint32_t soff = (uint32_t)(row * APITCH + col) * 2;
        cpasync16(so + BUF_BYTES + soff, B + (size_t)(n0 + row) * DD + k0 + col);
    }
}

__global__ __launch_bounds__(128, 4)
void gemm_out_tc(const float* __restrict__ bias, float* __restrict__ C)
{
    extern __shared__ char smem[];
    const uint32_t sbase = smem_to_u32(smem);

    const int tid = threadIdx.x;
    const int lane = tid & 31;
    const int wid = tid >> 5;           // 0..3
    const int wm = (wid >> 1) * 64;     // 0 or 64
    const int wn = (wid & 1) * 32;      // 0 or 32
    const int m0 = blockIdx.y * 128;
    const int n0 = blockIdx.x * 64;

    const int a_row = wm + (lane & 15);
    const int a_col = (lane >> 4) << 3;
    const int b_row = wn + ((lane >> 4) << 3) + (lane & 7);
    const int b_col = ((lane >> 3) & 1) << 3;

    float acc[4][4][4];
#pragma unroll
    for (int i = 0; i < 4; i++)
#pragma unroll
        for (int j = 0; j < 4; j++)
#pragma unroll
            for (int r = 0; r < 4; r++) acc[i][j][r] = 0.f;

    oload_stage(sbase, 0, g_ao16, g_wt16[3], m0, n0, 0, tid);
    cpcommit();
    oload_stage(sbase, 1, g_ao16, g_wt16[3], m0, n0, BK, tid);
    cpcommit();

    const int NT = DD / BK;             // 16
    for (int kt = 0; kt < NT; kt++) {
        if (kt + 2 < NT) {
            cpwait<1>();
        } else {
            cpwait<0>();
        }
        __syncthreads();

        const uint32_t st = sbase + (kt & 1) * OGEMM_STAGE;
#pragma unroll
        for (int ks = 0; ks < 4; ks++) {
            const int kofs = ks * 16;
            uint32_t ah[4][4], bh[2][4];
#pragma unroll
            for (int mt = 0; mt < 4; mt++) {
                uint32_t off = (uint32_t)((a_row + mt * 16) * APITCH + kofs + a_col) * 2;
                ldsm4(ah[mt], st + off);
            }
#pragma unroll
            for (int nt2 = 0; nt2 < 2; nt2++) {
                uint32_t off = (uint32_t)((b_row + nt2 * 16) * APITCH + kofs + b_col) * 2;
                ldsm4(bh[nt2], st + BUF_BYTES + off);
            }
#pragma unroll
            for (int mt = 0; mt < 4; mt++)
#pragma unroll
                for (int nt = 0; nt < 4; nt++)
                    mma_f16(acc[mt][nt], ah[mt], &bh[nt >> 1][(nt & 1) * 2]);
        }
        __syncthreads();
        if (kt + 2 < NT) {
            oload_stage(sbase, kt & 1, g_ao16, g_wt16[3], m0, n0, (kt + 2) * BK, tid);
            cpcommit();
        }
    }

#pragma unroll
    for (int mt = 0; mt < 4; mt++) {
        int row = m0 + wm + mt * 16 + (lane >> 2);
#pragma unroll
        for (int nt = 0; nt < 4; nt++) {
            int col = n0 + wn + nt * 8 + 2 * (lane & 3);
            float b0 = bias[col], b1 = bias[col + 1];
            size_t off0 = (size_t)row * DD + col;
            size_t off1 = (size_t)(row + 8) * DD + col;
            *(float2*)(C + off0) = make_float2(acc[mt][nt][0] + b0, acc[mt][nt][1] + b1);
            *(float2*)(C + off1) = make_float2(acc[mt][nt][2] + b0, acc[mt][nt][3] + b1);
        }
    }
}

// ---------------------------------------------------------------------------
// Tensor-core flash attention, causal, single-pass fp16.  (R12/R15 version)
// CTA: 64 q rows, 128 threads, 2-stage cp.async K/V pipeline, 4 CTAs/SM.
// Ones-column in V col 64 carries the row-sum l through the PV MMA.
// ---------------------------------------------------------------------------
#define VPITCH 88
#define AQ 0
#define AST 8192
#define SK 0
#define SV 8192
#define ASTAGE (8192 + 64 * VPITCH * 2)     // 19456
#define ATT_SMEM (AST + 2 * ASTAGE)         // 47104

__device__ __forceinline__ void attn_load_stage(uint32_t sb, int stage,
                                                const __half* gk,
                                                const __half* gv,
                                                int k0, int tid)
{
    uint32_t so = sb + AST + stage * ASTAGE;
#pragma unroll
    for (int i = 0; i < 4; i++) {
        int idx = tid + (i << 7);
        int r = idx >> 3, c = idx & 7;
        uint32_t offk = 128u * r + 16u * (c ^ (r & 7));
        size_t g = (size_t)(k0 + r) * DD + c * 8;
        cpasync16(so + SK + offk, gk + g);
        uint32_t offv = (uint32_t)(r * VPITCH + c * 8) * 2;
        cpasync16(so + SV + offv, gv + g);
    }
}

__global__ __launch_bounds__(128, 4) void attn_tc_kernel()
{
    extern __shared__ char sm[];
    const uint32_t sb = smem_to_u32(sm);
    const int tid = threadIdx.x;
    const int lane = tid & 31;
    const int wid = tid >> 5;
    const int bh = blockIdx.y;
    const int b = bh >> 4;
    const int h = bh & 15;
    const int q0 = (int)(gridDim.x - 1 - blockIdx.x) * 64;   // big tiles first

    const size_t tok0 = (size_t)(b * LL);
    const __half* gq = g_q16 + (tok0 + q0) * DD + h * 64;
    const __half* gk = g_k16 + tok0 * DD + h * 64;
    const __half* gv = g_v16 + tok0 * DD + h * 64;

    attn_load_stage(sb, 0, gk, gv, 0, tid);
    cpcommit();

#pragma unroll
    for (int s = 0; s < 2; s++) {
        char* vb = sm + AST + s * ASTAGE;
        for (int i = tid; i < 64 * 3; i += 128) {
            int r = i / 3, c = i % 3;
            uint32_t off = (uint32_t)(r * VPITCH + 64 + 8 * c) * 2;
            *(uint4*)(vb + SV + off) = make_uint4(0, 0, 0, 0);
        }
    }
    __syncthreads();
#pragma unroll
    for (int s = 0; s < 2; s++) {
        char* vb = sm + AST + s * ASTAGE;
        if (tid < 64) ((__half*)(vb + SV))[tid * VPITCH + 64] = __float2half(1.0f);
    }

#pragma unroll
    for (int i = 0; i < 4; i++) {
        int idx = tid + (i << 7);
        int r = idx >> 3, c = idx & 7;
        uint32_t off = 128u * r + 16u * (c ^ (r & 7));
        *(uint4*)(sm + AQ + off) = *(const uint4*)(gq + (size_t)r * DD + c * 8);
    }

    const int arow = 16 * wid + (lane & 15);
    const int ac = lane >> 4;
    const int asw = arow & 7;
    const int brow_in = ((lane >> 4) << 3) + (lane & 7);
    const int bc = (lane >> 3) & 1;
    const int bsw = brow_in & 7;
    const int vrow_in = (lane & 7) + ((lane >> 3) & 1) * 8;
    const int vnc = (lane >> 4);

    float oacc[9][4];
#pragma unroll
    for (int i = 0; i < 9; i++)
#pragma unroll
        for (int j = 0; j < 4; j++) oacc[i][j] = 0.f;
    float m2[2] = {-1e30f, -1e30f};

    const int nk = (q0 >> 6) + 1;
    for (int kt = 0; kt < nk; kt++) {
        if (kt + 1 < nk) {
            attn_load_stage(sb, (kt + 1) & 1, gk, gv, (kt + 1) * 64, tid);
            cpcommit();
            cpwait<1>();
        } else {
            cpwait<0>();
        }
        __syncthreads();
        const uint32_t st = sb + AST + (kt & 1) * ASTAGE;

        float sacc[8][4];
#pragma unroll
        for (int i = 0; i < 8; i++)
#pragma unroll
            for (int j = 0; j < 4; j++) sacc[i][j] = 0.f;

#pragma unroll
        for (int ks = 0; ks < 4; ks++) {
            uint32_t qf[4], kf[4][4];
            uint32_t ca = 16u * (uint32_t)((2 * ks + ac) ^ asw);
            ldsm4(qf, sb + AQ + 128u * arow + ca);
            uint32_t cb = 16u * (uint32_t)((2 * ks + bc) ^ bsw);
#pragma unroll
            for (int np = 0; np < 4; np++)
                ldsm4(kf[np], st + SK + 128u * (16 * np + brow_in) + cb);
#pragma unroll
            for (int nt = 0; nt < 8; nt++)
                mma_f16(sacc[nt], qf, &kf[nt >> 1][(nt & 1) * 2]);
        }

        if (kt == nk - 1) {
            const int r0g = 16 * wid + (lane >> 2);
#pragma unroll
            for (int nt = 0; nt < 8; nt++) {
                int kc = 8 * nt + 2 * (lane & 3);
                if (kc > r0g)     sacc[nt][0] = -1e30f;
                if (kc + 1 > r0g) sacc[nt][1] = -1e30f;
                if (kc > r0g + 8)     sacc[nt][2] = -1e30f;
                if (kc + 1 > r0g + 8) sacc[nt][3] = -1e30f;
            }
        }

        float mx0 = -1e30f, mx1 = -1e30f;
#pragma unroll
        for (int nt = 0; nt < 8; nt++) {
            mx0 = fmaxf(mx0, fmaxf(sacc[nt][0], sacc[nt][1]));
            mx1 = fmaxf(mx1, fmaxf(sacc[nt][2], sacc[nt][3]));
        }
        mx0 = fmaxf(mx0, __shfl_xor_sync(0xffffffffu, mx0, 1));
        mx0 = fmaxf(mx0, __shfl_xor_sync(0xffffffffu, mx0, 2));
        mx1 = fmaxf(mx1, __shfl_xor_sync(0xffffffffu, mx1, 1));
        mx1 = fmaxf(mx1, __shfl_xor_sync(0xffffffffu, mx1, 2));
        float m2n0 = fmaxf(m2[0], mx0 * L2E);
        float m2n1 = fmaxf(m2[1], mx1 * L2E);
        float al0 = exp2f(m2[0] - m2n0);
        float al1 = exp2f(m2[1] - m2n1);
        m2[0] = m2n0; m2[1] = m2n1;

        uint32_t pf[4][4];
#pragma unroll
        for (int ks = 0; ks < 4; ks++) {
            pf[ks][0] = ex2_f16x2(cvt_f16x2(fmaf(sacc[2*ks][1],   L2E, -m2n0),
                                            fmaf(sacc[2*ks][0],   L2E, -m2n0)));
            pf[ks][1] = ex2_f16x2(cvt_f16x2(fmaf(sacc[2*ks][3],   L2E, -m2n1),
                                            fmaf(sacc[2*ks][2],   L2E, -m2n1)));
            pf[ks][2] = ex2_f16x2(cvt_f16x2(fmaf(sacc[2*ks+1][1], L2E, -m2n0),
                                            fmaf(sacc[2*ks+1][0], L2E, -m2n0)));
            pf[ks][3] = ex2_f16x2(cvt_f16x2(fmaf(sacc[2*ks+1][3], L2E, -m2n1),
                                            fmaf(sacc[2*ks+1][2], L2E, -m2n1)));
        }
#pragma unroll
        for (int nt = 0; nt < 9; nt++) {
            oacc[nt][0] *= al0; oacc[nt][1] *= al0;
            oacc[nt][2] *= al1; oacc[nt][3] *= al1;
        }

#pragma unroll
        for (int ks = 0; ks < 4; ks++) {
            const uint32_t vrow = (uint32_t)(16 * ks + vrow_in) * (VPITCH * 2);
#pragma unroll
            for (int np = 0; np < 5; np++) {
                uint32_t vf[4];
                uint32_t voff = vrow + 16u * (uint32_t)(2 * np + vnc);
                ldsm4t(vf, st + SV + voff);
                mma_f16(oacc[2 * np], pf[ks], &vf[0]);
                if (np < 4) mma_f16(oacc[2 * np + 1], pf[ks], &vf[2]);
            }
        }
        __syncthreads();
    }

    const int src = lane & ~3;
    float l0 = __shfl_sync(0xffffffffu, oacc[8][0], src);
    float l1 = __shfl_sync(0xffffffffu, oacc[8][2], src);
    float i0 = 1.0f / l0;
    float i1 = 1.0f / l1;
    const int row0 = q0 + 16 * wid + (lane >> 2);
    __half* base16 = g_ao16 + tok0 * DD + h * 64;
#pragma unroll
    for (int nt = 0; nt < 8; nt++) {
        int col = 8 * nt + 2 * (lane & 3);
        size_t off0 = (size_t)row0 * DD + col;
        size_t off1 = (size_t)(row0 + 8) * DD + col;
        *(__half2*)(base16 + off0) = __floats2half2_rn(oacc[nt][0] * i0, oacc[nt][1] * i0);
        *(__half2*)(base16 + off1) = __floats2half2_rn(oacc[nt][2] * i1, oacc[nt][3] * i1);
    }
}

// ---------------------------------------------------------------------------
extern "C" void kernel_launch(void* const* d_in, const int* in_sizes, int n_in,
                              void* d_out, int out_size)
{
    (void)in_sizes; (void)n_in; (void)out_size;
    const float* x  = (const float*)d_in[0];
    const float* wq = (const float*)d_in[2];
    const float* bq = (const float*)d_in[3];
    const float* wk = (const float*)d_in[4];
    const float* bk = (const float*)d_in[5];
    const float* wv = (const float*)d_in[6];
    const float* bv = (const float*)d_in[7];
    const float* wo = (const float*)d_in[8];
    const float* bo = (const float*)d_in[9];
    float* out = (float*)d_out;

    cudaFuncSetAttribute(gemm_qkv_tc, cudaFuncAttributeMaxDynamicSharedMemorySize,
                         GEMM_SMEM_BYTES);
    cudaFuncSetAttribute(gemm_out_tc, cudaFuncAttributeMaxDynamicSharedMemorySize,
                         OGEMM_SMEM_BYTES);
    cudaFuncSetAttribute(attn_tc_kernel, cudaFuncAttributeMaxDynamicSharedMemorySize,
                         ATT_SMEM);

    prep_kernel<<<dim3(32, 32, 5), dim3(32, 32)>>>(x, wq, wk, wv, wo);
    gemm_qkv_tc<<<dim3(DD / 128, MM / 128, 3), 128, GEMM_SMEM_BYTES>>>(bq, bk, bv);
    attn_tc_kernel<<<dim3(LL / 64, BB * HH), 128, ATT_SMEM>>>();
    gemm_out_tc<<<dim3(DD / 64, MM / 128), 128, OGEMM_SMEM_BYTES>>>(bo, out);
}

// round 17
// speedup vs baseline: 1.0716x; 1.0198x over previous
#include <cuda_runtime.h>
#include <cuda_bf16.h>
#include <cuda_fp16.h>
#include <cstdint>
#include <math.h>

#define BB 2
#define LL 2048
#define DD 1024
#define HH 16
#define DHH 64
#define MM (BB * LL)   // 4096
#define L2E 1.4426950408889634f

// ---------------------------------------------------------------------------
// Scratch (__device__ globals: allocation-free rule)
// ---------------------------------------------------------------------------
__device__ __half g_x16[MM * DD];        // x in fp16
__device__ __half g_ao16[MM * DD];       // attention output in fp16
__device__ __half g_wt16[4][DD * DD];    // transposed weights [which][n][k] fp16

__device__ __half g_q16[MM * DD];        // Q fp16, pre-scaled by 0.125
__device__ __half g_k16[MM * DD];        // K fp16
__device__ __half g_v16[MM * DD];        // V fp16

// ---------------------------------------------------------------------------
// PTX helpers (portable sm_80+ subset; plain sm_103 target — no tcgen05)
// ---------------------------------------------------------------------------
__device__ __forceinline__ uint32_t smem_to_u32(const void* p) {
    uint32_t a;
    asm("{ .reg .u64 t; cvta.to.shared.u64 t, %1; cvt.u32.u64 %0, t; }"
        : "=r"(a) : "l"(p));
    return a;
}
__device__ __forceinline__ void cpasync16(uint32_t s, const void* g) {
    asm volatile("cp.async.cg.shared.global [%0], [%1], 16;" :: "r"(s), "l"(g));
}
__device__ __forceinline__ void cpcommit() {
    asm volatile("cp.async.commit_group;" ::: "memory");
}
template <int N>
__device__ __forceinline__ void cpwait() {
    asm volatile("cp.async.wait_group %0;" :: "n"(N) : "memory");
}
__device__ __forceinline__ void ldsm4(uint32_t* r, uint32_t addr) {
    asm volatile("ldmatrix.sync.aligned.m8n8.x4.shared.b16 {%0,%1,%2,%3}, [%4];"
                 : "=r"(r[0]), "=r"(r[1]), "=r"(r[2]), "=r"(r[3]) : "r"(addr));
}
__device__ __forceinline__ void ldsm4t(uint32_t* r, uint32_t addr) {
    asm volatile("ldmatrix.sync.aligned.m8n8.x4.trans.shared.b16 {%0,%1,%2,%3}, [%4];"
                 : "=r"(r[0]), "=r"(r[1]), "=r"(r[2]), "=r"(r[3]) : "r"(addr));
}
__device__ __forceinline__ void mma_f16(float* d, const uint32_t* a, const uint32_t* b) {
    asm volatile(
        "mma.sync.aligned.m16n8k16.row.col.f32.f16.f16.f32 "
        "{%0,%1,%2,%3}, {%4,%5,%6,%7}, {%8,%9}, {%0,%1,%2,%3};"
        : "+f"(d[0]), "+f"(d[1]), "+f"(d[2]), "+f"(d[3])
        : "r"(a[0]), "r"(a[1]), "r"(a[2]), "r"(a[3]), "r"(b[0]), "r"(b[1]));
}
__device__ __forceinline__ uint32_t cvt_f16x2(float hi, float lo) {
    uint32_t r;
    asm volatile("cvt.rn.f16x2.f32 %0, %1, %2;" : "=r"(r) : "f"(hi), "f"(lo));
    return r;
}
__device__ __forceinline__ uint32_t ex2_f16x2(uint32_t x) {
    uint32_t r;
    asm volatile("ex2.approx.f16x2 %0, %1;" : "=r"(r) : "r"(x));
    return r;
}

// ---------------------------------------------------------------------------
// Merged prep kernel: z=0..3 -> weight transpose+convert; z=4 -> x convert.
// ---------------------------------------------------------------------------
__global__ __launch_bounds__(1024) void prep_kernel(const float* __restrict__ x,
                                                    const float* __restrict__ wq,
                                                    const float* __restrict__ wk,
                                                    const float* __restrict__ wv,
                                                    const float* __restrict__ wo)
{
    int which = blockIdx.z;
    if (which == 4) {
        int i = (blockIdx.y * 32 + blockIdx.x) * 1024 + threadIdx.y * 32 + threadIdx.x;
        float4 v = ((const float4*)x)[i];
        __half2* hp = (__half2*)g_x16;
        hp[2 * i]     = __floats2half2_rn(v.x, v.y);
        hp[2 * i + 1] = __floats2half2_rn(v.z, v.w);
        return;
    }
    __shared__ float t[32][33];
    const float* w = (which == 0) ? wq : (which == 1) ? wk : (which == 2) ? wv : wo;
    int kk = blockIdx.y * 32 + threadIdx.y;
    int nn = blockIdx.x * 32 + threadIdx.x;
    t[threadIdx.y][threadIdx.x] = w[kk * DD + nn];
    __syncthreads();
    int on = blockIdx.x * 32 + threadIdx.y;
    int ok = blockIdx.y * 32 + threadIdx.x;
    g_wt16[which][on * DD + ok] = __float2half_rn(t[threadIdx.x][threadIdx.y]);
}

// ---------------------------------------------------------------------------
// Shared fp16 HMMA GEMM body: 128(M) x 64(N) CTA tile, warp tile 64x32 (2x2),
// BK=64, 2-stage cp.async, 4 CTAs/SM.
// mode 0: fp32 out + bias; mode 1: fp16 out *(bias, 0.125) (Q); mode 2: fp16 (K/V)
// ---------------------------------------------------------------------------
#define BK 64
#define APITCH 72
#define BUF_BYTES (128 * APITCH * 2)        // 18432 (128-row A operand)
#define OB_BYTES (64 * APITCH * 2)          // 9216  (64-row B operand)
#define GEMM_STAGE (BUF_BYTES + OB_BYTES)   // 27648
#define GEMM_SMEM_BYTES (2 * GEMM_STAGE)    // 55296 -> 4 CTAs/SM

__device__ __forceinline__ void load_stage(uint32_t sbase, int stage,
                                           const __half* __restrict__ A,
                                           const __half* __restrict__ B,
                                           int m0, int n0, int k0, int tid)
{
    uint32_t so = sbase + stage * GEMM_STAGE;
#pragma unroll
    for (int j = 0; j < 8; j++) {
        int c = tid + (j << 7);                 // 0..1023
        int row = c >> 3;                       // 0..127
        int col = (c & 7) << 3;
        uint32_t soff = (uint32_t)(row * APITCH + col) * 2;
        cpasync16(so + soff, A + (size_t)(m0 + row) * DD + k0 + col);
    }
#pragma unroll
    for (int j = 0; j < 4; j++) {
        int c = tid + (j << 7);                 // 0..511
        int row = c >> 3;                       // 0..63
        int col = (c & 7) << 3;
        uint32_t soff = (uint32_t)(row * APITCH + col) * 2;
        cpasync16(so + BUF_BYTES + soff, B + (size_t)(n0 + row) * DD + k0 + col);
    }
}

__device__ __forceinline__ void gemm_tc_body(const __half* __restrict__ A,
                                             const __half* __restrict__ B,
                                             const float* __restrict__ bias,
                                             int mode, __half* o16,
                                             float* __restrict__ C)
{
    extern __shared__ char smem[];
    const uint32_t sbase = smem_to_u32(smem);

    const int tid = threadIdx.x;
    const int lane = tid & 31;
    const int wid = tid >> 5;           // 0..3
    const int wm = (wid >> 1) * 64;     // 0 or 64
    const int wn = (wid & 1) * 32;      // 0 or 32
    const int m0 = blockIdx.y * 128;
    const int n0 = blockIdx.x * 64;

    const int a_row = wm + (lane & 15);
    const int a_col = (lane >> 4) << 3;
    const int b_row = wn + ((lane >> 4) << 3) + (lane & 7);
    const int b_col = ((lane >> 3) & 1) << 3;

    float acc[4][4][4];
#pragma unroll
    for (int i = 0; i < 4; i++)
#pragma unroll
        for (int j = 0; j < 4; j++)
#pragma unroll
            for (int r = 0; r < 4; r++) acc[i][j][r] = 0.f;

    load_stage(sbase, 0, A, B, m0, n0, 0, tid);
    cpcommit();
    load_stage(sbase, 1, A, B, m0, n0, BK, tid);
    cpcommit();

    const int NT = DD / BK;             // 16
    for (int kt = 0; kt < NT; kt++) {
        if (kt + 2 < NT) {
            cpwait<1>();
        } else {
            cpwait<0>();
        }
        __syncthreads();

        const uint32_t st = sbase + (kt & 1) * GEMM_STAGE;
#pragma unroll
        for (int ks = 0; ks < 4; ks++) {
            const int kofs = ks * 16;
            uint32_t ah[4][4], bh[2][4];
#pragma unroll
            for (int mt = 0; mt < 4; mt++) {
                uint32_t off = (uint32_t)((a_row + mt * 16) * APITCH + kofs + a_col) * 2;
                ldsm4(ah[mt], st + off);
            }
#pragma unroll
            for (int nt2 = 0; nt2 < 2; nt2++) {
                uint32_t off = (uint32_t)((b_row + nt2 * 16) * APITCH + kofs + b_col) * 2;
                ldsm4(bh[nt2], st + BUF_BYTES + off);
            }
#pragma unroll
            for (int mt = 0; mt < 4; mt++)
#pragma unroll
                for (int nt = 0; nt < 4; nt++)
                    mma_f16(acc[mt][nt], ah[mt], &bh[nt >> 1][(nt & 1) * 2]);
        }
        __syncthreads();
        if (kt + 2 < NT) {
            load_stage(sbase, kt & 1, A, B, m0, n0, (kt + 2) * BK, tid);
            cpcommit();
        }
    }

    const float sc = (mode == 1) ? 0.125f : 1.0f;
#pragma unroll
    for (int mt = 0; mt < 4; mt++) {
        int row = m0 + wm + mt * 16 + (lane >> 2);
#pragma unroll
        for (int nt = 0; nt < 4; nt++) {
            int col = n0 + wn + nt * 8 + 2 * (lane & 3);
            float b0 = bias[col], b1 = bias[col + 1];
            size_t off0 = (size_t)row * DD + col;
            size_t off1 = (size_t)(row + 8) * DD + col;
            if (mode == 0) {
                *(float2*)(C + off0) = make_float2(acc[mt][nt][0] + b0, acc[mt][nt][1] + b1);
                *(float2*)(C + off1) = make_float2(acc[mt][nt][2] + b0, acc[mt][nt][3] + b1);
            } else {
                float v0 = (acc[mt][nt][0] + b0) * sc, v1 = (acc[mt][nt][1] + b1) * sc;
                float v2 = (acc[mt][nt][2] + b0) * sc, v3 = (acc[mt][nt][3] + b1) * sc;
                *(__half2*)(o16 + off0) = __floats2half2_rn(v0, v1);
                *(__half2*)(o16 + off1) = __floats2half2_rn(v2, v3);
            }
        }
    }
}

__global__ __launch_bounds__(128, 4)
void gemm_qkv_tc(const float* __restrict__ bq, const float* __restrict__ bk,
                 const float* __restrict__ bv)
{
    const int z = blockIdx.z;
    if (z == 0)
        gemm_tc_body(g_x16, g_wt16[0], bq, 1, g_q16, nullptr);
    else if (z == 1)
        gemm_tc_body(g_x16, g_wt16[1], bk, 2, g_k16, nullptr);
    else
        gemm_tc_body(g_x16, g_wt16[2], bv, 2, g_v16, nullptr);
}

__global__ __launch_bounds__(128, 4)
void gemm_out_tc(const float* __restrict__ bo, float* __restrict__ out)
{
    gemm_tc_body(g_ao16, g_wt16[3], bo, 0, nullptr, out);
}

// ---------------------------------------------------------------------------
// Tensor-core flash attention, causal, single-pass fp16.  (R12/R15/R16 version)
// CTA: 64 q rows, 128 threads, 2-stage cp.async K/V pipeline, 4 CTAs/SM.
// Ones-column in V col 64 carries the row-sum l through the PV MMA.
// ---------------------------------------------------------------------------
#define VPITCH 88
#define AQ 0
#define AST 8192
#define SK 0
#define SV 8192
#define ASTAGE (8192 + 64 * VPITCH * 2)     // 19456
#define ATT_SMEM (AST + 2 * ASTAGE)         // 47104

__device__ __forceinline__ void attn_load_stage(uint32_t sb, int stage,
                                                const __half* gk,
                                                const __half* gv,
                                                int k0, int tid)
{
    uint32_t so = sb + AST + stage * ASTAGE;
#pragma unroll
    for (int i = 0; i < 4; i++) {
        int idx = tid + (i << 7);
        int r = idx >> 3, c = idx & 7;
        uint32_t offk = 128u * r + 16u * (c ^ (r & 7));
        size_t g = (size_t)(k0 + r) * DD + c * 8;
        cpasync16(so + SK + offk, gk + g);
        uint32_t offv = (uint32_t)(r * VPITCH + c * 8) * 2;
        cpasync16(so + SV + offv, gv + g);
    }
}

__global__ __launch_bounds__(128, 4) void attn_tc_kernel()
{
    extern __shared__ char sm[];
    const uint32_t sb = smem_to_u32(sm);
    const int tid = threadIdx.x;
    const int lane = tid & 31;
    const int wid = tid >> 5;
    const int bh = blockIdx.y;
    const int b = bh >> 4;
    const int h = bh & 15;
    const int q0 = (int)(gridDim.x - 1 - blockIdx.x) * 64;   // big tiles first

    const size_t tok0 = (size_t)(b * LL);
    const __half* gq = g_q16 + (tok0 + q0) * DD + h * 64;
    const __half* gk = g_k16 + tok0 * DD + h * 64;
    const __half* gv = g_v16 + tok0 * DD + h * 64;

    attn_load_stage(sb, 0, gk, gv, 0, tid);
    cpcommit();

#pragma unroll
    for (int s = 0; s < 2; s++) {
        char* vb = sm + AST + s * ASTAGE;
        for (int i = tid; i < 64 * 3; i += 128) {
            int r = i / 3, c = i % 3;
            uint32_t off = (uint32_t)(r * VPITCH + 64 + 8 * c) * 2;
            *(uint4*)(vb + SV + off) = make_uint4(0, 0, 0, 0);
        }
    }
    __syncthreads();
#pragma unroll
    for (int s = 0; s < 2; s++) {
        char* vb = sm + AST + s * ASTAGE;
        if (tid < 64) ((__half*)(vb + SV))[tid * VPITCH + 64] = __float2half(1.0f);
    }

#pragma unroll
    for (int i = 0; i < 4; i++) {
        int idx = tid + (i << 7);
        int r = idx >> 3, c = idx & 7;
        uint32_t off = 128u * r + 16u * (c ^ (r & 7));
        *(uint4*)(sm + AQ + off) = *(const uint4*)(gq + (size_t)r * DD + c * 8);
    }

    const int arow = 16 * wid + (lane & 15);
    const int ac = lane >> 4;
    const int asw = arow & 7;
    const int brow_in = ((lane >> 4) << 3) + (lane & 7);
    const int bc = (lane >> 3) & 1;
    const int bsw = brow_in & 7;
    const int vrow_in = (lane & 7) + ((lane >> 3) & 1) * 8;
    const int vnc = (lane >> 4);

    float oacc[9][4];
#pragma unroll
    for (int i = 0; i < 9; i++)
#pragma unroll
        for (int j = 0; j < 4; j++) oacc[i][j] = 0.f;
    float m2[2] = {-1e30f, -1e30f};

    const int nk = (q0 >> 6) + 1;
    for (int kt = 0; kt < nk; kt++) {
        if (kt + 1 < nk) {
            attn_load_stage(sb, (kt + 1) & 1, gk, gv, (kt + 1) * 64, tid);
            cpcommit();
            cpwait<1>();
        } else {
            cpwait<0>();
        }
        __syncthreads();
        const uint32_t st = sb + AST + (kt & 1) * ASTAGE;

        float sacc[8][4];
#pragma unroll
        for (int i = 0; i < 8; i++)
#pragma unroll
            for (int j = 0; j < 4; j++) sacc[i][j] = 0.f;

#pragma unroll
        for (int ks = 0; ks < 4; ks++) {
            uint32_t qf[4], kf[4][4];
            uint32_t ca = 16u * (uint32_t)((2 * ks + ac) ^ asw);
            ldsm4(qf, sb + AQ + 128u * arow + ca);
            uint32_t cb = 16u * (uint32_t)((2 * ks + bc) ^ bsw);
#pragma unroll
            for (int np = 0; np < 4; np++)
                ldsm4(kf[np], st + SK + 128u * (16 * np + brow_in) + cb);
#pragma unroll
            for (int nt = 0; nt < 8; nt++)
                mma_f16(sacc[nt], qf, &kf[nt >> 1][(nt & 1) * 2]);
        }

        if (kt == nk - 1) {
            const int r0g = 16 * wid + (lane >> 2);
#pragma unroll
            for (int nt = 0; nt < 8; nt++) {
                int kc = 8 * nt + 2 * (lane & 3);
                if (kc > r0g)     sacc[nt][0] = -1e30f;
                if (kc + 1 > r0g) sacc[nt][1] = -1e30f;
                if (kc > r0g + 8)     sacc[nt][2] = -1e30f;
                if (kc + 1 > r0g + 8) sacc[nt][3] = -1e30f;
            }
        }

        float mx0 = -1e30f, mx1 = -1e30f;
#pragma unroll
        for (int nt = 0; nt < 8; nt++) {
            mx0 = fmaxf(mx0, fmaxf(sacc[nt][0], sacc[nt][1]));
            mx1 = fmaxf(mx1, fmaxf(sacc[nt][2], sacc[nt][3]));
        }
        mx0 = fmaxf(mx0, __shfl_xor_sync(0xffffffffu, mx0, 1));
        mx0 = fmaxf(mx0, __shfl_xor_sync(0xffffffffu, mx0, 2));
        mx1 = fmaxf(mx1, __shfl_xor_sync(0xffffffffu, mx1, 1));
        mx1 = fmaxf(mx1, __shfl_xor_sync(0xffffffffu, mx1, 2));
        float m2n0 = fmaxf(m2[0], mx0 * L2E);
        float m2n1 = fmaxf(m2[1], mx1 * L2E);
        float al0 = exp2f(m2[0] - m2n0);
        float al1 = exp2f(m2[1] - m2n1);
        m2[0] = m2n0; m2[1] = m2n1;

        uint32_t pf[4][4];
#pragma unroll
        for (int ks = 0; ks < 4; ks++) {
            pf[ks][0] = ex2_f16x2(cvt_f16x2(fmaf(sacc[2*ks][1],   L2E, -m2n0),
                                            fmaf(sacc[2*ks][0],   L2E, -m2n0)));
            pf[ks][1] = ex2_f16x2(cvt_f16x2(fmaf(sacc[2*ks][3],   L2E, -m2n1),
                                            fmaf(sacc[2*ks][2],   L2E, -m2n1)));
            pf[ks][2] = ex2_f16x2(cvt_f16x2(fmaf(sacc[2*ks+1][1], L2E, -m2n0),
                                            fmaf(sacc[2*ks+1][0], L2E, -m2n0)));
            pf[ks][3] = ex2_f16x2(cvt_f16x2(fmaf(sacc[2*ks+1][3], L2E, -m2n1),
                                            fmaf(sacc[2*ks+1][2], L2E, -m2n1)));
        }
#pragma unroll
        for (int nt = 0; nt < 9; nt++) {
            oacc[nt][0] *= al0; oacc[nt][1] *= al0;
            oacc[nt][2] *= al1; oacc[nt][3] *= al1;
        }

#pragma unroll
        for (int ks = 0; ks < 4; ks++) {
            const uint32_t vrow = (uint32_t)(16 * ks + vrow_in) * (VPITCH * 2);
#pragma unroll
            for (int np = 0; np < 5; np++) {
                uint32_t vf[4];
                uint32_t voff = vrow + 16u * (uint32_t)(2 * np + vnc);
                ldsm4t(vf, st + SV + voff);
                mma_f16(oacc[2 * np], pf[ks], &vf[0]);
                if (np < 4) mma_f16(oacc[2 * np + 1], pf[ks], &vf[2]);
            }
        }
        __syncthreads();
    }

    const int src = lane & ~3;
    float l0 = __shfl_sync(0xffffffffu, oacc[8][0], src);
    float l1 = __shfl_sync(0xffffffffu, oacc[8][2], src);
    float i0 = 1.0f / l0;
    float i1 = 1.0f / l1;
    const int row0 = q0 + 16 * wid + (lane >> 2);
    __half* base16 = g_ao16 + tok0 * DD + h * 64;
#pragma unroll
    for (int nt = 0; nt < 8; nt++) {
        int col = 8 * nt + 2 * (lane & 3);
        size_t off0 = (size_t)row0 * DD + col;
        size_t off1 = (size_t)(row0 + 8) * DD + col;
        *(__half2*)(base16 + off0) = __floats2half2_rn(oacc[nt][0] * i0, oacc[nt][1] * i0);
        *(__half2*)(base16 + off1) = __floats2half2_rn(oacc[nt][2] * i1, oacc[nt][3] * i1);
    }
}

// ---------------------------------------------------------------------------
extern "C" void kernel_launch(void* const* d_in, const int* in_sizes, int n_in,
                              void* d_out, int out_size)
{
    (void)in_sizes; (void)n_in; (void)out_size;
    const float* x  = (const float*)d_in[0];
    const float* wq = (const float*)d_in[2];
    const float* bq = (const float*)d_in[3];
    const float* wk = (const float*)d_in[4];
    const float* bk = (const float*)d_in[5];
    const float* wv = (const float*)d_in[6];
    const float* bv = (const float*)d_in[7];
    const float* wo = (const float*)d_in[8];
    const float* bo = (const float*)d_in[9];
    float* out = (float*)d_out;

    cudaFuncSetAttribute(gemm_qkv_tc, cudaFuncAttributeMaxDynamicSharedMemorySize,
                         GEMM_SMEM_BYTES);
    cudaFuncSetAttribute(gemm_out_tc, cudaFuncAttributeMaxDynamicSharedMemorySize,
                         GEMM_SMEM_BYTES);
    cudaFuncSetAttribute(attn_tc_kernel, cudaFuncAttributeMaxDynamicSharedMemorySize,
                         ATT_SMEM);

    prep_kernel<<<dim3(32, 32, 5), dim3(32, 32)>>>(x, wq, wk, wv, wo);
    gemm_qkv_tc<<<dim3(DD / 64, MM / 128, 3), 128, GEMM_SMEM_BYTES>>>(bq, bk, bv);
    attn_tc_kernel<<<dim3(LL / 64, BB * HH), 128, ATT_SMEM>>>();
    gemm_out_tc<<<dim3(DD / 64, MM / 128), 128, GEMM_SMEM_BYTES>>>(bo, out);
}